// round 1
// baseline (speedup 1.0000x reference)
#include <cuda_runtime.h>
#include <cuda_bf16.h>
#include <math.h>

// ---------------------------------------------------------------------------
// TRAlign: cross-attention block
//   N = M = 4096, REGION_DIM = 144, LLM_DIM = 3584, H = 4, HD = 36, VHD = 896
//
// Pipeline (all fp32, separate kernels on default stream):
//   1. Q = target @ wq + b                      [4096,144]
//   2. K = source @ wk + b                      [4096,144]
//   3. V[h] = value @ wv[h] + b[h]              stored as [4096, 3584] (col off h*896)
//   4. S[h] = (Q_h @ K_h^T) / 6                 [4,4096,4096]
//   5. softmax rows of S
//   6. X = target @ resid_w + resid_b           [4096,3584]
//   7. X += S[h] @ V[h]   (per head, disjoint col blocks)
//   8. layernorm rows of X (in place)
//   9. out = X @ out_w + out_b
// ---------------------------------------------------------------------------

#define NQ 4096
#define MS 4096
#define RD 144
#define LD 3584
#define NH 4
#define HD 36
#define VHD 896

// Scratch (device globals -> no allocation at launch time)
__device__ float g_Q[(size_t)NQ * RD];
__device__ float g_K[(size_t)MS * RD];
__device__ float g_V[(size_t)MS * LD];
__device__ float g_S[(size_t)NH * NQ * MS];   // 268 MB
__device__ float g_X[(size_t)NQ * LD];

// ---------------------------------------------------------------------------
// Generic batched SGEMM: C = alpha * A @ op(B) [+ bias] [+ C]
// 128x128 block tile, BK=16, 256 threads, 8x8 per thread.
// TRANSB: B element (k,n) read as B[n*ldb + k] (i.e. C = A @ B^T).
// ---------------------------------------------------------------------------
template <bool TRANSB>
__global__ __launch_bounds__(256)
void sgemm_kernel(const float* __restrict__ A, const float* __restrict__ B,
                  float* __restrict__ C,
                  int Mm, int Nn, int Kk, int lda, int ldb, int ldc,
                  long long strideA, long long strideB, long long strideC,
                  float alpha,
                  const float* __restrict__ bias, long long strideBias,
                  int accum)
{
    const int BM = 128, BN = 128, BK = 16;
    __shared__ float As[BK][BM];
    __shared__ float Bs[BK][BN];

    const int z = blockIdx.z;
    A += (size_t)z * strideA;
    B += (size_t)z * strideB;
    C += (size_t)z * strideC;
    if (bias) bias += (size_t)z * strideBias;

    const int row0 = blockIdx.y * BM;
    const int col0 = blockIdx.x * BN;
    const int tid = threadIdx.x;
    const int tx = tid % 16;           // column group
    const int ty = tid / 16;           // row group

    float acc[8][8];
#pragma unroll
    for (int i = 0; i < 8; i++)
#pragma unroll
        for (int j = 0; j < 8; j++) acc[i][j] = 0.f;

    for (int k0 = 0; k0 < Kk; k0 += BK) {
        // Load A tile (BM x BK) transposed into As[k][m]
#pragma unroll
        for (int it = 0; it < (BM * BK) / 256; it++) {
            int idx = tid + it * 256;
            int m = idx / BK, k = idx % BK;
            int gm = row0 + m, gk = k0 + k;
            float v = 0.f;
            if (gm < Mm && gk < Kk) v = A[(size_t)gm * lda + gk];
            As[k][m] = v;
        }
        // Load B tile (BK x BN) into Bs[k][n]
#pragma unroll
        for (int it = 0; it < (BK * BN) / 256; it++) {
            int idx = tid + it * 256;
            int k = idx / BN, n = idx % BN;
            int gk = k0 + k, gn = col0 + n;
            float v = 0.f;
            if (gk < Kk && gn < Nn) {
                if (TRANSB) v = B[(size_t)gn * ldb + gk];
                else        v = B[(size_t)gk * ldb + gn];
            }
            Bs[k][n] = v;
        }
        __syncthreads();

#pragma unroll
        for (int k = 0; k < BK; k++) {
            float a[8], b[8];
#pragma unroll
            for (int i = 0; i < 8; i++) a[i] = As[k][ty * 8 + i];
#pragma unroll
            for (int j = 0; j < 8; j++) b[j] = Bs[k][tx * 8 + j];
#pragma unroll
            for (int i = 0; i < 8; i++)
#pragma unroll
                for (int j = 0; j < 8; j++)
                    acc[i][j] = fmaf(a[i], b[j], acc[i][j]);
        }
        __syncthreads();
    }

    // Epilogue
#pragma unroll
    for (int i = 0; i < 8; i++) {
        int gm = row0 + ty * 8 + i;
        if (gm >= Mm) continue;
#pragma unroll
        for (int j = 0; j < 8; j++) {
            int gn = col0 + tx * 8 + j;
            if (gn >= Nn) continue;
            float v = alpha * acc[i][j];
            if (bias) v += bias[gn];
            size_t off = (size_t)gm * ldc + gn;
            if (accum) v += C[off];
            C[off] = v;
        }
    }
}

// ---------------------------------------------------------------------------
// Row softmax over 4096-wide rows (one block of 256 threads per row).
// ---------------------------------------------------------------------------
__global__ __launch_bounds__(256)
void softmax_kernel(float* __restrict__ S)
{
    float* p = S + (size_t)blockIdx.x * 4096;
    const int t = threadIdx.x;
    float v[16];
    float mx = -1e30f;
#pragma unroll
    for (int i = 0; i < 16; i++) {
        v[i] = p[t + i * 256];
        mx = fmaxf(mx, v[i]);
    }
    __shared__ float red[256];
    red[t] = mx;
    __syncthreads();
#pragma unroll
    for (int s = 128; s > 0; s >>= 1) {
        if (t < s) red[t] = fmaxf(red[t], red[t + s]);
        __syncthreads();
    }
    mx = red[0];
    __syncthreads();

    float sum = 0.f;
#pragma unroll
    for (int i = 0; i < 16; i++) {
        v[i] = __expf(v[i] - mx);
        sum += v[i];
    }
    red[t] = sum;
    __syncthreads();
#pragma unroll
    for (int s = 128; s > 0; s >>= 1) {
        if (t < s) red[t] += red[t + s];
        __syncthreads();
    }
    const float inv = 1.f / red[0];
#pragma unroll
    for (int i = 0; i < 16; i++) p[t + i * 256] = v[i] * inv;
}

// ---------------------------------------------------------------------------
// Row layernorm over 3584-wide rows (one block of 256 threads per row).
// ---------------------------------------------------------------------------
__global__ __launch_bounds__(256)
void layernorm_kernel(float* __restrict__ X,
                      const float* __restrict__ gamma,
                      const float* __restrict__ beta)
{
    const int D = 3584;        // 256 * 14
    float* p = X + (size_t)blockIdx.x * D;
    const int t = threadIdx.x;
    float v[14];
    float s = 0.f;
#pragma unroll
    for (int i = 0; i < 14; i++) {
        v[i] = p[t + i * 256];
        s += v[i];
    }
    __shared__ float red[256];
    red[t] = s;
    __syncthreads();
#pragma unroll
    for (int st = 128; st > 0; st >>= 1) {
        if (t < st) red[t] += red[t + st];
        __syncthreads();
    }
    const float mean = red[0] / (float)D;
    __syncthreads();

    float sq = 0.f;
#pragma unroll
    for (int i = 0; i < 14; i++) {
        float d = v[i] - mean;
        sq += d * d;
    }
    red[t] = sq;
    __syncthreads();
#pragma unroll
    for (int st = 128; st > 0; st >>= 1) {
        if (t < st) red[t] += red[t + st];
        __syncthreads();
    }
    const float inv = rsqrtf(red[0] / (float)D + 1e-5f);
    __syncthreads();
#pragma unroll
    for (int i = 0; i < 14; i++) {
        int c = t + i * 256;
        p[c] = (v[i] - mean) * inv * gamma[c] + beta[c];
    }
}

// ---------------------------------------------------------------------------
// Launcher
// ---------------------------------------------------------------------------
static inline dim3 gemm_grid(int Mm, int Nn, int Z)
{
    return dim3((Nn + 127) / 128, (Mm + 127) / 128, Z);
}

extern "C" void kernel_launch(void* const* d_in, const int* in_sizes, int n_in,
                              void* d_out, int out_size)
{
    const float* target  = (const float*)d_in[0];   // [4096,144]
    const float* source  = (const float*)d_in[1];   // [4096,3584]
    const float* value   = (const float*)d_in[2];   // [4096,3584]
    const float* wq_w    = (const float*)d_in[3];   // [144,144]
    const float* wq_b    = (const float*)d_in[4];   // [144]
    const float* wk_w    = (const float*)d_in[5];   // [3584,144]
    const float* wk_b    = (const float*)d_in[6];   // [144]
    const float* wv_w    = (const float*)d_in[7];   // [4,3584,896]
    const float* wv_b    = (const float*)d_in[8];   // [4,896]
    const float* resid_w = (const float*)d_in[9];   // [144,3584]
    const float* resid_b = (const float*)d_in[10];  // [3584]
    const float* out_w   = (const float*)d_in[11];  // [3584,3584]
    const float* out_b   = (const float*)d_in[12];  // [3584]
    const float* ln_g    = (const float*)d_in[13];  // [3584]
    const float* ln_b    = (const float*)d_in[14];  // [3584]
    float* out = (float*)d_out;                     // [4096,3584]

    float *pQ, *pK, *pV, *pS, *pX;
    cudaGetSymbolAddress((void**)&pQ, g_Q);
    cudaGetSymbolAddress((void**)&pK, g_K);
    cudaGetSymbolAddress((void**)&pV, g_V);
    cudaGetSymbolAddress((void**)&pS, g_S);
    cudaGetSymbolAddress((void**)&pX, g_X);

    // 1. Q = target @ wq_w + wq_b            [4096,144]
    sgemm_kernel<false><<<gemm_grid(NQ, RD, 1), 256>>>(
        target, wq_w, pQ, NQ, RD, RD, RD, RD, RD,
        0, 0, 0, 1.f, wq_b, 0, 0);

    // 2. K = source @ wk_w + wk_b            [4096,144]
    sgemm_kernel<false><<<gemm_grid(MS, RD, 1), 256>>>(
        source, wk_w, pK, MS, RD, LD, LD, RD, RD,
        0, 0, 0, 1.f, wk_b, 0, 0);

    // 3. V[h] = value @ wv_w[h] + wv_b[h]    -> g_V[m, h*896 + d], ldc = 3584
    sgemm_kernel<false><<<gemm_grid(MS, VHD, NH), 256>>>(
        value, wv_w, pV, MS, VHD, LD, LD, VHD, LD,
        0, (long long)LD * VHD, VHD, 1.f, wv_b, VHD, 0);

    // 4. S[h] = (Q_h @ K_h^T) / sqrt(36)     [4,4096,4096]
    sgemm_kernel<true><<<gemm_grid(NQ, MS, NH), 256>>>(
        pQ, pK, pS, NQ, MS, HD, RD, RD, MS,
        HD, HD, (long long)NQ * MS, 1.f / 6.f, nullptr, 0, 0);

    // 5. softmax over rows
    softmax_kernel<<<NH * NQ, 256>>>(pS);

    // 6. X = target @ resid_w + resid_b      [4096,3584]
    sgemm_kernel<false><<<gemm_grid(NQ, LD, 1), 256>>>(
        target, resid_w, pX, NQ, LD, RD, RD, LD, LD,
        0, 0, 0, 1.f, resid_b, 0, 0);

    // 7. X[:, h*896:(h+1)*896] += S[h] @ V[h]
    sgemm_kernel<false><<<gemm_grid(NQ, VHD, NH), 256>>>(
        pS, pV, pX, NQ, VHD, MS, MS, LD, LD,
        (long long)NQ * MS, VHD, VHD, 1.f, nullptr, 0, 1);

    // 8. layernorm rows of X (in place)
    layernorm_kernel<<<NQ, 256>>>(pX, ln_g, ln_b);

    // 9. out = X @ out_w + out_b
    sgemm_kernel<false><<<gemm_grid(NQ, LD, 1), 256>>>(
        pX, out_w, out, NQ, LD, LD, LD, LD, LD,
        0, 0, 0, 1.f, out_b, 0, 0);
}

// round 3
// speedup vs baseline: 3.8227x; 3.8227x over previous
#include <cuda_runtime.h>
#include <cuda_bf16.h>
#include <cstdint>
#include <math.h>

// ===========================================================================
// TRAlign on mma.sync (HMMA) tensor cores — sm_103-safe baseline PTX only.
// All GEMMs are bf16 with K-folded split compensation:
//   A_ext = [hi(A) | lo(A) | hi(A)]   (row-major, K-major)
//   B_ext = [hi(B) | hi(B) | lo(B)]   (row-major [N,K'], K-major)
//   A_ext @ B_ext^T = Ahi*Bhi + Alo*Bhi + Ahi*Blo  ~ fp32 accuracy (~1e-5)
// ===========================================================================

#define NQ 4096
#define LD 3584
#define RD 144
#define NH 4
#define HD 36
#define VHD 896

// K' sizes (padded to multiples of 64)
#define KP_RD   448     // 3*144 = 432 -> 448
#define KP_LD   10752   // 3*3584
#define KP_HD   128     // 3*36 = 108 -> 128
#define KP_MS   12288   // 3*4096

// ---------------- device scratch ----------------
__device__ __align__(128) __nv_bfloat16 g_te [(size_t)NQ * KP_RD];
__device__ __align__(128) __nv_bfloat16 g_se [(size_t)NQ * KP_LD];
__device__ __align__(128) __nv_bfloat16 g_ve [(size_t)NQ * KP_LD];
__device__ __align__(128) __nv_bfloat16 g_wqe[(size_t)256 * KP_RD];
__device__ __align__(128) __nv_bfloat16 g_wke[(size_t)256 * KP_LD];
__device__ __align__(128) __nv_bfloat16 g_wve[(size_t)NH * VHD * KP_LD];
__device__ __align__(128) __nv_bfloat16 g_re [(size_t)LD * KP_RD];
__device__ __align__(128) __nv_bfloat16 g_oe [(size_t)LD * KP_LD];
__device__ __align__(128) float         g_Qf [(size_t)NQ * 256];
__device__ __align__(128) float         g_Kf [(size_t)NQ * 256];
__device__ __align__(128) __nv_bfloat16 g_Qe [(size_t)NH * NQ * KP_HD];
__device__ __align__(128) __nv_bfloat16 g_Ke [(size_t)NH * NQ * KP_HD];
__device__ __align__(128) float         g_S  [(size_t)NH * NQ * NQ];     // 268 MB
__device__ __align__(128) __nv_bfloat16 g_Se [(size_t)NH * NQ * KP_MS];
__device__ __align__(128) float         g_Vf [(size_t)NH * NQ * VHD];
__device__ __align__(128) __nv_bfloat16 g_Vte[(size_t)NH * VHD * KP_MS];
__device__ __align__(128) float         g_Xf [(size_t)NQ * LD];
__device__ __align__(128) __nv_bfloat16 g_Xe [(size_t)NQ * KP_LD];

// ---------------- PTX helpers (baseline, sm_80+) ----------------
__device__ __forceinline__ uint32_t smem_u32_of(const void* p) {
    uint32_t a;
    asm("{ .reg .u64 t; cvta.to.shared.u64 t, %1; cvt.u32.u64 %0, t; }"
        : "=r"(a) : "l"(p));
    return a;
}

__device__ __forceinline__ void cp16(uint32_t dst, const void* src) {
    asm volatile("cp.async.cg.shared.global [%0], [%1], 16;" :: "r"(dst), "l"(src));
}
__device__ __forceinline__ void cp_commit() {
    asm volatile("cp.async.commit_group;");
}
__device__ __forceinline__ void cp_wait2() {
    asm volatile("cp.async.wait_group 2;");
}
__device__ __forceinline__ void cp_wait0() {
    asm volatile("cp.async.wait_group 0;");
}

__device__ __forceinline__ void ldsm4(uint32_t* r, uint32_t addr) {
    asm volatile("ldmatrix.sync.aligned.m8n8.x4.shared.b16 {%0,%1,%2,%3}, [%4];"
                 : "=r"(r[0]), "=r"(r[1]), "=r"(r[2]), "=r"(r[3]) : "r"(addr));
}

__device__ __forceinline__ void mma16816(float* c, const uint32_t* a,
                                         uint32_t b0, uint32_t b1) {
    asm volatile(
        "mma.sync.aligned.m16n8k16.row.col.f32.bf16.bf16.f32 "
        "{%0,%1,%2,%3}, {%4,%5,%6,%7}, {%8,%9}, {%0,%1,%2,%3};"
        : "+f"(c[0]), "+f"(c[1]), "+f"(c[2]), "+f"(c[3])
        : "r"(a[0]), "r"(a[1]), "r"(a[2]), "r"(a[3]), "r"(b0), "r"(b1));
}

// ---------------- bf16 split helpers ----------------
__device__ __forceinline__ __nv_bfloat16 bf_hi(float f) { return __float2bfloat16(f); }
__device__ __forceinline__ __nv_bfloat16 bf_lo(float f) {
    float hi = __bfloat162float(__float2bfloat16(f));
    return __float2bfloat16(f - hi);
}

// ===========================================================================
// HMMA GEMM: C[M, N] = alpha * A @ B^T (+bias) (+C)
// A [M, K] bf16 K-major, B [N, K] bf16 K-major, K % 64 == 0, N % 128 == 0,
// M % 128 == 0. Tile 128x128, BK=64, 3 cp.async stages, 256 threads.
// smem per stage: A 128x72 bf16 (pitch 144B) + B 128x72 bf16 = 36864 B.
// ===========================================================================
#define STAGE_BYTES 36864
#define NSTAGE 3
#define MMA_SMEM (NSTAGE * STAGE_BYTES)

__device__ __forceinline__ void load_stage(uint32_t sbase,
                                           const __nv_bfloat16* A, const __nv_bfloat16* B,
                                           int lda, int ldb, int row0, int col0, int k0,
                                           int tid)
{
#pragma unroll
    for (int i = 0; i < 4; i++) {
        int c = tid + i * 256;              // 0..1023
        int r = c >> 3, cc = c & 7;         // row, 16B chunk within 64-col tile
        cp16(sbase + r * 144 + cc * 16,
             A + (size_t)(row0 + r) * lda + k0 + cc * 8);
        cp16(sbase + 18432 + r * 144 + cc * 16,
             B + (size_t)(col0 + r) * ldb + k0 + cc * 8);
    }
}

__global__ __launch_bounds__(256)
void mma_gemm(const __nv_bfloat16* __restrict__ A, const __nv_bfloat16* __restrict__ B,
              float* __restrict__ C, int K, int lda, int ldb, int ldc,
              long long sA, long long sB, long long sC,
              float alpha, const float* __restrict__ bias, int biasN, long long sBias,
              int accum)
{
    extern __shared__ char smem[];
    const uint32_t sb = smem_u32_of(smem);
    const int tid = threadIdx.x;
    const int warp = tid >> 5, lane = tid & 31;
    const int wm = warp & 1;                // M half (64 rows)
    const int wn = warp >> 1;               // N quarter (32 cols)

    A += (size_t)blockIdx.z * sA;
    B += (size_t)blockIdx.z * sB;
    C += (size_t)blockIdx.z * sC;
    if (bias) bias += (size_t)blockIdx.z * sBias;
    const int row0 = blockIdx.y * 128, col0 = blockIdx.x * 128;

    float acc[4][4][4];
#pragma unroll
    for (int i = 0; i < 4; i++)
#pragma unroll
        for (int j = 0; j < 4; j++)
#pragma unroll
            for (int v = 0; v < 4; v++) acc[i][j][v] = 0.f;

    const int KT = K >> 6;

    // prefetch up to NSTAGE-1 stages
#pragma unroll
    for (int s = 0; s < NSTAGE - 1; s++) {
        if (s < KT) { load_stage(sb + s * STAGE_BYTES, A, B, lda, ldb, row0, col0, s * 64, tid); }
        cp_commit();
    }

    // ldmatrix lane addressing (within a 16x16 bf16 region, pitch 144B):
    const int lrow = lane & 15;             // row within 16
    const int lkof = (lane >> 4) * 16;      // byte offset for k-half (8 bf16)

    for (int kt = 0; kt < KT; kt++) {
        int ldk = kt + NSTAGE - 1;
        if (ldk < KT) {
            load_stage(sb + (ldk % NSTAGE) * STAGE_BYTES, A, B, lda, ldb, row0, col0, ldk * 64, tid);
            cp_commit();
            cp_wait2();
        } else {
            cp_commit();        // keep group count consistent
            cp_wait0();
        }
        __syncthreads();

        uint32_t abase = sb + (kt % NSTAGE) * STAGE_BYTES + (wm * 64) * 144;
        uint32_t bbase = sb + (kt % NSTAGE) * STAGE_BYTES + 18432 + (wn * 32) * 144;

#pragma unroll
        for (int k16 = 0; k16 < 4; k16++) {
            uint32_t a[4][4];
#pragma unroll
            for (int mf = 0; mf < 4; mf++)
                ldsm4(a[mf], abase + (mf * 16 + lrow) * 144 + k16 * 32 + lkof);
            uint32_t b[2][4];
#pragma unroll
            for (int nf2 = 0; nf2 < 2; nf2++)
                ldsm4(b[nf2], bbase + (nf2 * 16 + lrow) * 144 + k16 * 32 + lkof);
            // b[g][0]=n-frag(2g) k0-7, b[g][1]=n-frag(2g+1) k0-7,
            // b[g][2]=n-frag(2g) k8-15, b[g][3]=n-frag(2g+1) k8-15
#pragma unroll
            for (int mf = 0; mf < 4; mf++)
#pragma unroll
                for (int nf = 0; nf < 4; nf++)
                    mma16816(acc[mf][nf], a[mf], b[nf >> 1][nf & 1], b[nf >> 1][2 + (nf & 1)]);
        }
        __syncthreads();
    }

    // -------- epilogue: direct global stores (float2) --------
    const int qr = lane >> 2;           // 0..7
    const int qc = (lane & 3) * 2;      // 0,2,4,6
#pragma unroll
    for (int mf = 0; mf < 4; mf++) {
#pragma unroll
        for (int nf = 0; nf < 4; nf++) {
            int gr = row0 + wm * 64 + mf * 16 + qr;
            int gc = col0 + wn * 32 + nf * 8 + qc;
            float b0 = 0.f, b1 = 0.f;
            if (bias) {
                if (gc + 0 < biasN) b0 = bias[gc + 0];
                if (gc + 1 < biasN) b1 = bias[gc + 1];
            }
#pragma unroll
            for (int h = 0; h < 2; h++) {
                int r = gr + h * 8;
                float v0 = alpha * acc[mf][nf][h * 2 + 0] + b0;
                float v1 = alpha * acc[mf][nf][h * 2 + 1] + b1;
                float* cp = C + (size_t)r * ldc + gc;
                if (accum) { v0 += cp[0]; v1 += cp[1]; }
                float2 o = make_float2(v0, v1);
                *(float2*)cp = o;
            }
        }
    }
}

// ===========================================================================
// Conversion kernels
// ===========================================================================
// A-side row expansion: fp32 [M,Kin] -> bf16 [M,Kp] = [hi | lo | hi | 0pad]
__global__ void ext_rows(const float* __restrict__ in, __nv_bfloat16* __restrict__ out,
                         int Kin, int ldin, int Kp)
{
    int c = blockIdx.x * 256 + threadIdx.x;
    if (c >= Kp) return;
    size_t row = blockIdx.y;
    __nv_bfloat16 r;
    if (c < Kin)            r = bf_hi(in[row * ldin + c]);
    else if (c < 2 * Kin)   r = bf_lo(in[row * ldin + c - Kin]);
    else if (c < 3 * Kin)   r = bf_hi(in[row * ldin + c - 2 * Kin]);
    else                    r = __float2bfloat16(0.f);
    out[row * (size_t)Kp + c] = r;
}

// B-side transpose expansion: W fp32 [K, Nn] (ldw) -> bf16 [Np, Kp],
// out[n, b*Kin + k] = (b<2 ? hi : lo)(W[k, n]); rows n in [Nn,Np) zero.
__global__ void ext_transpose(const float* __restrict__ in, __nv_bfloat16* __restrict__ out,
                              int Kin, int Nn, int Np, int Kp, int ldw,
                              long long sIn, long long sOut)
{
    __shared__ float t[32][33];
    int b = blockIdx.z % 3, z = blockIdx.z / 3;
    in  += (size_t)z * sIn;
    out += (size_t)z * sOut;
    int k0 = blockIdx.x * 32, n0 = blockIdx.y * 32;
    int tx = threadIdx.x, ty = threadIdx.y;   // 32 x 8
#pragma unroll
    for (int i = 0; i < 4; i++) {
        int k = k0 + ty + i * 8, n = n0 + tx;
        t[ty + i * 8][tx] = (k < Kin && n < Nn) ? in[(size_t)k * ldw + n] : 0.f;
    }
    __syncthreads();
#pragma unroll
    for (int i = 0; i < 4; i++) {
        int n = n0 + ty + i * 8, k = k0 + tx;
        if (n < Np && k < Kin) {
            float f = t[tx][ty + i * 8];
            out[(size_t)n * Kp + (size_t)b * Kin + k] = (b == 2) ? bf_lo(f) : bf_hi(f);
        }
    }
}

// Split Q/K fp32 [4096,256] into per-head ext [H,4096,128].
// orderB=0 -> [hi|lo|hi] (A side), orderB=1 -> [hi|hi|lo] (B side).
__global__ void qk_split(const float* __restrict__ Qf, __nv_bfloat16* __restrict__ out, int orderB)
{
    int h = blockIdx.y, row = blockIdx.x, c = threadIdx.x;   // 128 threads
    const float* src = Qf + (size_t)row * 256 + h * HD;
    __nv_bfloat16 o;
    if (c >= 3 * HD) o = __float2bfloat16(0.f);
    else {
        int b = c / HD;
        float f = src[c - b * HD];
        bool isLo = orderB ? (b == 2) : (b == 1);
        o = isLo ? bf_lo(f) : bf_hi(f);
    }
    out[((size_t)h * NQ + row) * KP_HD + c] = o;
}

// Softmax (row of 4096) fused with A-side ext write [hi|lo|hi] into [*,12288].
__global__ __launch_bounds__(256)
void softmax_ext(const float* __restrict__ S, __nv_bfloat16* __restrict__ out)
{
    const float* p = S + (size_t)blockIdx.x * 4096;
    __nv_bfloat16* q = out + (size_t)blockIdx.x * KP_MS;
    const int t = threadIdx.x;
    float v[16];
    float mx = -1e30f;
#pragma unroll
    for (int i = 0; i < 16; i++) { v[i] = p[t + i * 256]; mx = fmaxf(mx, v[i]); }
    __shared__ float red[256];
    red[t] = mx; __syncthreads();
#pragma unroll
    for (int s = 128; s > 0; s >>= 1) { if (t < s) red[t] = fmaxf(red[t], red[t + s]); __syncthreads(); }
    mx = red[0]; __syncthreads();
    float sum = 0.f;
#pragma unroll
    for (int i = 0; i < 16; i++) { v[i] = __expf(v[i] - mx); sum += v[i]; }
    red[t] = sum; __syncthreads();
#pragma unroll
    for (int s = 128; s > 0; s >>= 1) { if (t < s) red[t] += red[t + s]; __syncthreads(); }
    const float inv = 1.f / red[0];
#pragma unroll
    for (int i = 0; i < 16; i++) {
        int c = t + i * 256;
        float pv = v[i] * inv;
        __nv_bfloat16 hi = __float2bfloat16(pv);
        q[c] = hi;
        q[8192 + c] = hi;
        q[4096 + c] = __float2bfloat16(pv - __bfloat162float(hi));
    }
}

// LayerNorm (row of 3584) fused with A-side ext write into [*,10752].
__global__ __launch_bounds__(256)
void ln_ext(const float* __restrict__ X, __nv_bfloat16* __restrict__ out,
            const float* __restrict__ g, const float* __restrict__ b)
{
    const int D = LD;   // 3584 = 14*256
    const float* p = X + (size_t)blockIdx.x * D;
    __nv_bfloat16* q = out + (size_t)blockIdx.x * KP_LD;
    const int t = threadIdx.x;
    float v[14];
    float s = 0.f;
#pragma unroll
    for (int i = 0; i < 14; i++) { v[i] = p[t + i * 256]; s += v[i]; }
    __shared__ float red[256];
    red[t] = s; __syncthreads();
#pragma unroll
    for (int st = 128; st > 0; st >>= 1) { if (t < st) red[t] += red[t + st]; __syncthreads(); }
    const float mean = red[0] / (float)D; __syncthreads();
    float sq = 0.f;
#pragma unroll
    for (int i = 0; i < 14; i++) { float d = v[i] - mean; sq += d * d; }
    red[t] = sq; __syncthreads();
#pragma unroll
    for (int st = 128; st > 0; st >>= 1) { if (t < st) red[t] += red[t + st]; __syncthreads(); }
    const float inv = rsqrtf(red[0] / (float)D + 1e-5f);
#pragma unroll
    for (int i = 0; i < 14; i++) {
        int c = t + i * 256;
        float y = (v[i] - mean) * inv * g[c] + b[c];
        __nv_bfloat16 hi = __float2bfloat16(y);
        q[c] = hi;
        q[7168 + c] = hi;
        q[3584 + c] = __float2bfloat16(y - __bfloat162float(hi));
    }
}

// ===========================================================================
// Launcher
// ===========================================================================
extern "C" void kernel_launch(void* const* d_in, const int* in_sizes, int n_in,
                              void* d_out, int out_size)
{
    const float* target  = (const float*)d_in[0];
    const float* source  = (const float*)d_in[1];
    const float* value   = (const float*)d_in[2];
    const float* wq_w    = (const float*)d_in[3];
    const float* wq_b    = (const float*)d_in[4];
    const float* wk_w    = (const float*)d_in[5];
    const float* wk_b    = (const float*)d_in[6];
    const float* wv_w    = (const float*)d_in[7];
    const float* wv_b    = (const float*)d_in[8];
    const float* resid_w = (const float*)d_in[9];
    const float* resid_b = (const float*)d_in[10];
    const float* out_w   = (const float*)d_in[11];
    const float* out_b   = (const float*)d_in[12];
    const float* ln_g    = (const float*)d_in[13];
    const float* ln_b    = (const float*)d_in[14];
    float* out = (float*)d_out;

    __nv_bfloat16 *pte, *pse, *pve, *pwqe, *pwke, *pwve, *pre, *poe;
    __nv_bfloat16 *pQe, *pKe, *pSe, *pVte, *pXe;
    float *pQf, *pKf, *pS, *pVf, *pXf;
    cudaGetSymbolAddress((void**)&pte, g_te);
    cudaGetSymbolAddress((void**)&pse, g_se);
    cudaGetSymbolAddress((void**)&pve, g_ve);
    cudaGetSymbolAddress((void**)&pwqe, g_wqe);
    cudaGetSymbolAddress((void**)&pwke, g_wke);
    cudaGetSymbolAddress((void**)&pwve, g_wve);
    cudaGetSymbolAddress((void**)&pre, g_re);
    cudaGetSymbolAddress((void**)&poe, g_oe);
    cudaGetSymbolAddress((void**)&pQf, g_Qf);
    cudaGetSymbolAddress((void**)&pKf, g_Kf);
    cudaGetSymbolAddress((void**)&pQe, g_Qe);
    cudaGetSymbolAddress((void**)&pKe, g_Ke);
    cudaGetSymbolAddress((void**)&pS, g_S);
    cudaGetSymbolAddress((void**)&pSe, g_Se);
    cudaGetSymbolAddress((void**)&pVf, g_Vf);
    cudaGetSymbolAddress((void**)&pVte, g_Vte);
    cudaGetSymbolAddress((void**)&pXf, g_Xf);
    cudaGetSymbolAddress((void**)&pXe, g_Xe);

    cudaFuncSetAttribute(mma_gemm, cudaFuncAttributeMaxDynamicSharedMemorySize, MMA_SMEM);

    // zero pads of column-padded B buffers (cols [3*144, 448))
    cudaMemsetAsync(pwqe, 0, (size_t)256 * KP_RD * sizeof(__nv_bfloat16));
    cudaMemsetAsync(pre, 0, (size_t)LD * KP_RD * sizeof(__nv_bfloat16));

    // --- operand expansions ---
    ext_rows<<<dim3(2, NQ), 256>>>(target, pte, RD, RD, KP_RD);
    ext_rows<<<dim3(42, NQ), 256>>>(source, pse, LD, LD, KP_LD);
    ext_rows<<<dim3(42, NQ), 256>>>(value, pve, LD, LD, KP_LD);

    ext_transpose<<<dim3(5, 8, 3), dim3(32, 8)>>>(wq_w, pwqe, RD, RD, 256, KP_RD, RD, 0, 0);
    ext_transpose<<<dim3(112, 8, 3), dim3(32, 8)>>>(wk_w, pwke, LD, RD, 256, KP_LD, RD, 0, 0);
    ext_transpose<<<dim3(112, 28, 12), dim3(32, 8)>>>(wv_w, pwve, LD, VHD, VHD, KP_LD, VHD,
                                                      (long long)LD * VHD, (long long)VHD * KP_LD);
    ext_transpose<<<dim3(5, 112, 3), dim3(32, 8)>>>(resid_w, pre, RD, LD, LD, KP_RD, LD, 0, 0);
    ext_transpose<<<dim3(112, 112, 3), dim3(32, 8)>>>(out_w, poe, LD, LD, LD, KP_LD, LD, 0, 0);

    // --- Q/K projections: [4096,256] fp32 (N padded, bias guarded to 144) ---
    mma_gemm<<<dim3(2, 32, 1), 256, MMA_SMEM>>>(
        pte, pwqe, pQf, KP_RD, KP_RD, KP_RD, 256, 0, 0, 0, 1.f, wq_b, RD, 0, 0);
    mma_gemm<<<dim3(2, 32, 1), 256, MMA_SMEM>>>(
        pse, pwke, pKf, KP_LD, KP_LD, KP_LD, 256, 0, 0, 0, 1.f, wk_b, RD, 0, 0);
    qk_split<<<dim3(NQ, NH), 128>>>(pQf, pQe, 0);
    qk_split<<<dim3(NQ, NH), 128>>>(pKf, pKe, 1);

    // --- scores: S[h] = (Q_h @ K_h^T) / 6 ---
    mma_gemm<<<dim3(32, 32, NH), 256, MMA_SMEM>>>(
        pQe, pKe, pS, KP_HD, KP_HD, KP_HD, NQ,
        (long long)NQ * KP_HD, (long long)NQ * KP_HD, (long long)NQ * NQ,
        1.f / 6.f, nullptr, 0, 0, 0);

    // --- softmax + ext ---
    softmax_ext<<<NH * NQ, 256>>>(pS, pSe);

    // --- V projection: Vf[h] = value @ wv[h] + b[h] ---
    mma_gemm<<<dim3(7, 32, NH), 256, MMA_SMEM>>>(
        pve, pwve, pVf, KP_LD, KP_LD, KP_LD, VHD,
        0, (long long)VHD * KP_LD, (long long)NQ * VHD,
        1.f, wv_b, VHD, VHD, 0);

    // --- V^T ext for ctx GEMM ---
    ext_transpose<<<dim3(128, 28, 12), dim3(32, 8)>>>(pVf, pVte, NQ, VHD, VHD, KP_MS, VHD,
                                                      (long long)NQ * VHD, (long long)VHD * KP_MS);

    // --- residual projection: Xf = target @ resid_w + b ---
    mma_gemm<<<dim3(28, 32, 1), 256, MMA_SMEM>>>(
        pte, pre, pXf, KP_RD, KP_RD, KP_RD, LD, 0, 0, 0, 1.f, resid_b, LD, 0, 0);

    // --- ctx: Xf[:, h*896 ..] += attn[h] @ V[h] ---
    mma_gemm<<<dim3(7, 32, NH), 256, MMA_SMEM>>>(
        pSe, pVte, pXf, KP_MS, KP_MS, KP_MS, LD,
        (long long)NQ * KP_MS, (long long)VHD * KP_MS, (long long)VHD,
        1.f, nullptr, 0, 0, 1);

    // --- layernorm + ext ---
    ln_ext<<<NQ, 256>>>(pXf, pXe, ln_g, ln_b);

    // --- output projection ---
    mma_gemm<<<dim3(28, 32, 1), 256, MMA_SMEM>>>(
        pXe, poe, out, KP_LD, KP_LD, KP_LD, LD, 0, 0, 0, 1.f, out_b, LD, 0, 0);
}

// round 4
// speedup vs baseline: 4.2633x; 1.1153x over previous
#include <cuda_runtime.h>
#include <cuda_bf16.h>
#include <cstdint>
#include <math.h>

// ===========================================================================
// TRAlign on mma.sync (HMMA) tensor cores — sm_103-safe baseline PTX only.
// GEMMs are bf16 with K-folded split compensation:
//   3-term: A_ext=[hi|lo|hi] x B_ext=[hi|hi|lo]  -> ~2^-16 accuracy
//   2-term (ctx only): P=[hi|lo] x V^T=[hi|hi]   -> ~2^-9 on ctx (small vs x)
// ===========================================================================

#define NQ 4096
#define LD 3584
#define RD 144
#define NH 4
#define HD 36
#define VHD 896

// K' sizes (padded to multiples of 64)
#define KP_RD   448     // 3*144 = 432 -> 448
#define KP_LD   10752   // 3*3584
#define KP_HD   128     // 3*36 = 108 -> 128
#define KP_MS   8192    // 2*4096 (ctx 2-term)

// ---------------- device scratch ----------------
__device__ __align__(128) __nv_bfloat16 g_te [(size_t)NQ * KP_RD];
__device__ __align__(128) __nv_bfloat16 g_se [(size_t)NQ * KP_LD];
__device__ __align__(128) __nv_bfloat16 g_ve [(size_t)NQ * KP_LD];
__device__ __align__(128) __nv_bfloat16 g_wqe[(size_t)256 * KP_RD];
__device__ __align__(128) __nv_bfloat16 g_wke[(size_t)256 * KP_LD];
__device__ __align__(128) __nv_bfloat16 g_wve[(size_t)NH * VHD * KP_LD];
__device__ __align__(128) __nv_bfloat16 g_re [(size_t)LD * KP_RD];
__device__ __align__(128) __nv_bfloat16 g_oe [(size_t)LD * KP_LD];
__device__ __align__(128) float         g_Qf [(size_t)NQ * 256];
__device__ __align__(128) float         g_Kf [(size_t)NQ * 256];
__device__ __align__(128) __nv_bfloat16 g_Qe [(size_t)NH * NQ * KP_HD];
__device__ __align__(128) __nv_bfloat16 g_Ke [(size_t)NH * NQ * KP_HD];
__device__ __align__(128) float         g_S  [(size_t)NH * NQ * NQ];     // 268 MB
__device__ __align__(128) __nv_bfloat16 g_Se [(size_t)NH * NQ * KP_MS];
__device__ __align__(128) float         g_Vf [(size_t)NH * NQ * VHD];
__device__ __align__(128) __nv_bfloat16 g_Vte[(size_t)NH * VHD * KP_MS];
__device__ __align__(128) float         g_Xf [(size_t)NQ * LD];
__device__ __align__(128) __nv_bfloat16 g_Xe [(size_t)NQ * KP_LD];

// ---------------- PTX helpers (baseline, sm_80+) ----------------
__device__ __forceinline__ uint32_t smem_u32_of(const void* p) {
    uint32_t a;
    asm("{ .reg .u64 t; cvta.to.shared.u64 t, %1; cvt.u32.u64 %0, t; }"
        : "=r"(a) : "l"(p));
    return a;
}

__device__ __forceinline__ void cp16(uint32_t dst, const void* src) {
    asm volatile("cp.async.cg.shared.global [%0], [%1], 16;" :: "r"(dst), "l"(src));
}
__device__ __forceinline__ void cp_commit() {
    asm volatile("cp.async.commit_group;");
}
__device__ __forceinline__ void cp_wait1() {
    asm volatile("cp.async.wait_group 1;");
}

__device__ __forceinline__ void ldsm4(uint32_t* r, uint32_t addr) {
    asm volatile("ldmatrix.sync.aligned.m8n8.x4.shared.b16 {%0,%1,%2,%3}, [%4];"
                 : "=r"(r[0]), "=r"(r[1]), "=r"(r[2]), "=r"(r[3]) : "r"(addr));
}

__device__ __forceinline__ void mma16816(float* c, const uint32_t* a,
                                         uint32_t b0, uint32_t b1) {
    asm volatile(
        "mma.sync.aligned.m16n8k16.row.col.f32.bf16.bf16.f32 "
        "{%0,%1,%2,%3}, {%4,%5,%6,%7}, {%8,%9}, {%0,%1,%2,%3};"
        : "+f"(c[0]), "+f"(c[1]), "+f"(c[2]), "+f"(c[3])
        : "r"(a[0]), "r"(a[1]), "r"(a[2]), "r"(a[3]), "r"(b0), "r"(b1));
}

// ---------------- bf16 split helpers ----------------
__device__ __forceinline__ __nv_bfloat16 bf_hi(float f) { return __float2bfloat16(f); }
__device__ __forceinline__ __nv_bfloat16 bf_lo(float f) {
    float hi = __bfloat162float(__float2bfloat16(f));
    return __float2bfloat16(f - hi);
}

// ===========================================================================
// HMMA GEMM: C[M, N] = alpha * A @ B^T (+bias) (+C)
// A [M, K] bf16 K-major, B [N, K] bf16 K-major, K % 64 == 0, N % 128 == 0,
// M % 128 == 0. Tile 128x128, BK=64, 3 cp.async stages, 256 threads,
// one __syncthreads per mainloop iteration, 2 CTAs per SM.
// smem per stage: A 128x72 bf16 (pitch 144B) + B 128x72 bf16 = 36864 B.
// ===========================================================================
#define STAGE_BYTES 36864
#define NSTAGE 3
#define MMA_SMEM (NSTAGE * STAGE_BYTES)

__device__ __forceinline__ void load_stage(uint32_t sbase,
                                           const __nv_bfloat16* A, const __nv_bfloat16* B,
                                           int lda, int ldb, int row0, int col0, int k0,
                                           int tid)
{
#pragma unroll
    for (int i = 0; i < 4; i++) {
        int c = tid + i * 256;              // 0..1023
        int r = c >> 3, cc = c & 7;         // row, 16B chunk within 64-col tile
        cp16(sbase + r * 144 + cc * 16,
             A + (size_t)(row0 + r) * lda + k0 + cc * 8);
        cp16(sbase + 18432 + r * 144 + cc * 16,
             B + (size_t)(col0 + r) * ldb + k0 + cc * 8);
    }
}

__global__ __launch_bounds__(256, 2)
void mma_gemm(const __nv_bfloat16* __restrict__ A, const __nv_bfloat16* __restrict__ B,
              float* __restrict__ C, int K, int lda, int ldb, int ldc,
              long long sA, long long sB, long long sC,
              float alpha, const float* __restrict__ bias, int biasN, long long sBias,
              int accum)
{
    extern __shared__ char smem[];
    const uint32_t sb = smem_u32_of(smem);
    const int tid = threadIdx.x;
    const int warp = tid >> 5, lane = tid & 31;
    const int wm = warp & 1;                // M half (64 rows)
    const int wn = warp >> 1;               // N quarter (32 cols)

    A += (size_t)blockIdx.z * sA;
    B += (size_t)blockIdx.z * sB;
    C += (size_t)blockIdx.z * sC;
    if (bias) bias += (size_t)blockIdx.z * sBias;
    const int row0 = blockIdx.y * 128, col0 = blockIdx.x * 128;

    float acc[4][4][4];
#pragma unroll
    for (int i = 0; i < 4; i++)
#pragma unroll
        for (int j = 0; j < 4; j++)
#pragma unroll
            for (int v = 0; v < 4; v++) acc[i][j][v] = 0.f;

    const int KT = K >> 6;

    // prefetch NSTAGE-1 stages
#pragma unroll
    for (int s = 0; s < NSTAGE - 1; s++) {
        if (s < KT) load_stage(sb + s * STAGE_BYTES, A, B, lda, ldb, row0, col0, s * 64, tid);
        cp_commit();
    }

    // ldmatrix lane addressing (within a 16x16 bf16 region, pitch 144B):
    const int lrow = lane & 15;             // row within 16
    const int lkof = (lane >> 4) * 16;      // byte offset for k-half (8 bf16)

    for (int kt = 0; kt < KT; kt++) {
        cp_wait1();              // stage kt group complete (this thread)
        __syncthreads();         // all threads see stage kt; stage (kt-1)%3 free

        int ldk = kt + NSTAGE - 1;
        if (ldk < KT)
            load_stage(sb + (ldk % NSTAGE) * STAGE_BYTES, A, B, lda, ldb, row0, col0, ldk * 64, tid);
        cp_commit();

        uint32_t abase = sb + (kt % NSTAGE) * STAGE_BYTES + (wm * 64) * 144;
        uint32_t bbase = sb + (kt % NSTAGE) * STAGE_BYTES + 18432 + (wn * 32) * 144;

#pragma unroll
        for (int k16 = 0; k16 < 4; k16++) {
            uint32_t a[4][4];
#pragma unroll
            for (int mf = 0; mf < 4; mf++)
                ldsm4(a[mf], abase + (mf * 16 + lrow) * 144 + k16 * 32 + lkof);
            uint32_t b[2][4];
#pragma unroll
            for (int nf2 = 0; nf2 < 2; nf2++)
                ldsm4(b[nf2], bbase + (nf2 * 16 + lrow) * 144 + k16 * 32 + lkof);
#pragma unroll
            for (int mf = 0; mf < 4; mf++)
#pragma unroll
                for (int nf = 0; nf < 4; nf++)
                    mma16816(acc[mf][nf], a[mf], b[nf >> 1][nf & 1], b[nf >> 1][2 + (nf & 1)]);
        }
    }

    // -------- epilogue: direct global stores (float2) --------
    const int qr = lane >> 2;           // 0..7
    const int qc = (lane & 3) * 2;      // 0,2,4,6
#pragma unroll
    for (int mf = 0; mf < 4; mf++) {
#pragma unroll
        for (int nf = 0; nf < 4; nf++) {
            int gr = row0 + wm * 64 + mf * 16 + qr;
            int gc = col0 + wn * 32 + nf * 8 + qc;
            float b0 = 0.f, b1 = 0.f;
            if (bias) {
                if (gc + 0 < biasN) b0 = bias[gc + 0];
                if (gc + 1 < biasN) b1 = bias[gc + 1];
            }
#pragma unroll
            for (int h = 0; h < 2; h++) {
                int r = gr + h * 8;
                float v0 = alpha * acc[mf][nf][h * 2 + 0] + b0;
                float v1 = alpha * acc[mf][nf][h * 2 + 1] + b1;
                float* cp = C + (size_t)r * ldc + gc;
                if (accum) { v0 += cp[0]; v1 += cp[1]; }
                float2 o = make_float2(v0, v1);
                *(float2*)cp = o;
            }
        }
    }
}

// ===========================================================================
// Conversion kernels
// ===========================================================================
// A-side row expansion: fp32 [M,Kin] -> bf16 [M,Kp] = [hi | lo | hi | 0pad]
__global__ void ext_rows(const float* __restrict__ in, __nv_bfloat16* __restrict__ out,
                         int Kin, int ldin, int Kp)
{
    int c = blockIdx.x * 256 + threadIdx.x;
    if (c >= Kp) return;
    size_t row = blockIdx.y;
    __nv_bfloat16 r;
    if (c < Kin)            r = bf_hi(in[row * ldin + c]);
    else if (c < 2 * Kin)   r = bf_lo(in[row * ldin + c - Kin]);
    else if (c < 3 * Kin)   r = bf_hi(in[row * ldin + c - 2 * Kin]);
    else                    r = __float2bfloat16(0.f);
    out[row * (size_t)Kp + c] = r;
}

// B-side transpose expansion: W fp32 [K, Nn] (ldw) -> bf16 [Np, Kp],
// out[n, b*Kin + k] = (b==loIdx ? lo : hi)(W[k, n]); rows n in [Nn,Np) zero.
// terms = number of K-fold copies; gridDim.z = batches * terms.
__global__ void ext_transpose(const float* __restrict__ in, __nv_bfloat16* __restrict__ out,
                              int Kin, int Nn, int Np, int Kp, int ldw,
                              long long sIn, long long sOut, int terms, int loIdx)
{
    __shared__ float t[32][33];
    int b = blockIdx.z % terms, z = blockIdx.z / terms;
    in  += (size_t)z * sIn;
    out += (size_t)z * sOut;
    int k0 = blockIdx.x * 32, n0 = blockIdx.y * 32;
    int tx = threadIdx.x, ty = threadIdx.y;   // 32 x 8
#pragma unroll
    for (int i = 0; i < 4; i++) {
        int k = k0 + ty + i * 8, n = n0 + tx;
        t[ty + i * 8][tx] = (k < Kin && n < Nn) ? in[(size_t)k * ldw + n] : 0.f;
    }
    __syncthreads();
#pragma unroll
    for (int i = 0; i < 4; i++) {
        int n = n0 + ty + i * 8, k = k0 + tx;
        if (n < Np && k < Kin) {
            float f = t[tx][ty + i * 8];
            out[(size_t)n * Kp + (size_t)b * Kin + k] = (b == loIdx) ? bf_lo(f) : bf_hi(f);
        }
    }
}

// Split Q/K fp32 [4096,256] into per-head ext [H,4096,128].
// orderB=0 -> [hi|lo|hi] (A side), orderB=1 -> [hi|hi|lo] (B side).
__global__ void qk_split(const float* __restrict__ Qf, __nv_bfloat16* __restrict__ out, int orderB)
{
    int h = blockIdx.y, row = blockIdx.x, c = threadIdx.x;   // 128 threads
    const float* src = Qf + (size_t)row * 256 + h * HD;
    __nv_bfloat16 o;
    if (c >= 3 * HD) o = __float2bfloat16(0.f);
    else {
        int b = c / HD;
        float f = src[c - b * HD];
        bool isLo = orderB ? (b == 2) : (b == 1);
        o = isLo ? bf_lo(f) : bf_hi(f);
    }
    out[((size_t)h * NQ + row) * KP_HD + c] = o;
}

// Softmax (row of 4096) fused with A-side 2-term ext write [hi|lo] into [*,8192].
__global__ __launch_bounds__(256)
void softmax_ext(const float* __restrict__ S, __nv_bfloat16* __restrict__ out)
{
    const float* p = S + (size_t)blockIdx.x * 4096;
    __nv_bfloat16* q = out + (size_t)blockIdx.x * KP_MS;
    const int t = threadIdx.x;
    float v[16];
    float mx = -1e30f;
#pragma unroll
    for (int i = 0; i < 16; i++) { v[i] = p[t + i * 256]; mx = fmaxf(mx, v[i]); }
    __shared__ float red[256];
    red[t] = mx; __syncthreads();
#pragma unroll
    for (int s = 128; s > 0; s >>= 1) { if (t < s) red[t] = fmaxf(red[t], red[t + s]); __syncthreads(); }
    mx = red[0]; __syncthreads();
    float sum = 0.f;
#pragma unroll
    for (int i = 0; i < 16; i++) { v[i] = __expf(v[i] - mx); sum += v[i]; }
    red[t] = sum; __syncthreads();
#pragma unroll
    for (int s = 128; s > 0; s >>= 1) { if (t < s) red[t] += red[t + s]; __syncthreads(); }
    const float inv = 1.f / red[0];
#pragma unroll
    for (int i = 0; i < 16; i++) {
        int c = t + i * 256;
        float pv = v[i] * inv;
        __nv_bfloat16 hi = __float2bfloat16(pv);
        q[c] = hi;
        q[4096 + c] = __float2bfloat16(pv - __bfloat162float(hi));
    }
}

// LayerNorm (row of 3584) fused with A-side ext write into [*,10752].
__global__ __launch_bounds__(256)
void ln_ext(const float* __restrict__ X, __nv_bfloat16* __restrict__ out,
            const float* __restrict__ g, const float* __restrict__ b)
{
    const int D = LD;   // 3584 = 14*256
    const float* p = X + (size_t)blockIdx.x * D;
    __nv_bfloat16* q = out + (size_t)blockIdx.x * KP_LD;
    const int t = threadIdx.x;
    float v[14];
    float s = 0.f;
#pragma unroll
    for (int i = 0; i < 14; i++) { v[i] = p[t + i * 256]; s += v[i]; }
    __shared__ float red[256];
    red[t] = s; __syncthreads();
#pragma unroll
    for (int st = 128; st > 0; st >>= 1) { if (t < st) red[t] += red[t + st]; __syncthreads(); }
    const float mean = red[0] / (float)D; __syncthreads();
    float sq = 0.f;
#pragma unroll
    for (int i = 0; i < 14; i++) { float d = v[i] - mean; sq += d * d; }
    red[t] = sq; __syncthreads();
#pragma unroll
    for (int st = 128; st > 0; st >>= 1) { if (t < st) red[t] += red[t + st]; __syncthreads(); }
    const float inv = rsqrtf(red[0] / (float)D + 1e-5f);
#pragma unroll
    for (int i = 0; i < 14; i++) {
        int c = t + i * 256;
        float y = (v[i] - mean) * inv * g[c] + b[c];
        __nv_bfloat16 hi = __float2bfloat16(y);
        q[c] = hi;
        q[7168 + c] = hi;
        q[3584 + c] = __float2bfloat16(y - __bfloat162float(hi));
    }
}

// ===========================================================================
// Launcher
// ===========================================================================
extern "C" void kernel_launch(void* const* d_in, const int* in_sizes, int n_in,
                              void* d_out, int out_size)
{
    const float* target  = (const float*)d_in[0];
    const float* source  = (const float*)d_in[1];
    const float* value   = (const float*)d_in[2];
    const float* wq_w    = (const float*)d_in[3];
    const float* wq_b    = (const float*)d_in[4];
    const float* wk_w    = (const float*)d_in[5];
    const float* wk_b    = (const float*)d_in[6];
    const float* wv_w    = (const float*)d_in[7];
    const float* wv_b    = (const float*)d_in[8];
    const float* resid_w = (const float*)d_in[9];
    const float* resid_b = (const float*)d_in[10];
    const float* out_w   = (const float*)d_in[11];
    const float* out_b   = (const float*)d_in[12];
    const float* ln_g    = (const float*)d_in[13];
    const float* ln_b    = (const float*)d_in[14];
    float* out = (float*)d_out;

    __nv_bfloat16 *pte, *pse, *pve, *pwqe, *pwke, *pwve, *pre, *poe;
    __nv_bfloat16 *pQe, *pKe, *pSe, *pVte, *pXe;
    float *pQf, *pKf, *pS, *pVf, *pXf;
    cudaGetSymbolAddress((void**)&pte, g_te);
    cudaGetSymbolAddress((void**)&pse, g_se);
    cudaGetSymbolAddress((void**)&pve, g_ve);
    cudaGetSymbolAddress((void**)&pwqe, g_wqe);
    cudaGetSymbolAddress((void**)&pwke, g_wke);
    cudaGetSymbolAddress((void**)&pwve, g_wve);
    cudaGetSymbolAddress((void**)&pre, g_re);
    cudaGetSymbolAddress((void**)&poe, g_oe);
    cudaGetSymbolAddress((void**)&pQf, g_Qf);
    cudaGetSymbolAddress((void**)&pKf, g_Kf);
    cudaGetSymbolAddress((void**)&pQe, g_Qe);
    cudaGetSymbolAddress((void**)&pKe, g_Ke);
    cudaGetSymbolAddress((void**)&pS, g_S);
    cudaGetSymbolAddress((void**)&pSe, g_Se);
    cudaGetSymbolAddress((void**)&pVf, g_Vf);
    cudaGetSymbolAddress((void**)&pVte, g_Vte);
    cudaGetSymbolAddress((void**)&pXf, g_Xf);
    cudaGetSymbolAddress((void**)&pXe, g_Xe);

    cudaFuncSetAttribute(mma_gemm, cudaFuncAttributeMaxDynamicSharedMemorySize, MMA_SMEM);

    // zero pads of column-padded B buffers (cols [3*144, 448))
    cudaMemsetAsync(pwqe, 0, (size_t)256 * KP_RD * sizeof(__nv_bfloat16));
    cudaMemsetAsync(pre, 0, (size_t)LD * KP_RD * sizeof(__nv_bfloat16));

    // --- operand expansions ---
    ext_rows<<<dim3(2, NQ), 256>>>(target, pte, RD, RD, KP_RD);
    ext_rows<<<dim3(42, NQ), 256>>>(source, pse, LD, LD, KP_LD);
    ext_rows<<<dim3(42, NQ), 256>>>(value, pve, LD, LD, KP_LD);

    ext_transpose<<<dim3(5, 8, 3), dim3(32, 8)>>>(wq_w, pwqe, RD, RD, 256, KP_RD, RD, 0, 0, 3, 2);
    ext_transpose<<<dim3(112, 8, 3), dim3(32, 8)>>>(wk_w, pwke, LD, RD, 256, KP_LD, RD, 0, 0, 3, 2);
    ext_transpose<<<dim3(112, 28, 12), dim3(32, 8)>>>(wv_w, pwve, LD, VHD, VHD, KP_LD, VHD,
                                                      (long long)LD * VHD, (long long)VHD * KP_LD, 3, 2);
    ext_transpose<<<dim3(5, 112, 3), dim3(32, 8)>>>(resid_w, pre, RD, LD, LD, KP_RD, LD, 0, 0, 3, 2);
    ext_transpose<<<dim3(112, 112, 3), dim3(32, 8)>>>(out_w, poe, LD, LD, LD, KP_LD, LD, 0, 0, 3, 2);

    // --- Q/K projections: [4096,256] fp32 (N padded, bias guarded to 144) ---
    mma_gemm<<<dim3(2, 32, 1), 256, MMA_SMEM>>>(
        pte, pwqe, pQf, KP_RD, KP_RD, KP_RD, 256, 0, 0, 0, 1.f, wq_b, RD, 0, 0);
    mma_gemm<<<dim3(2, 32, 1), 256, MMA_SMEM>>>(
        pse, pwke, pKf, KP_LD, KP_LD, KP_LD, 256, 0, 0, 0, 1.f, wk_b, RD, 0, 0);
    qk_split<<<dim3(NQ, NH), 128>>>(pQf, pQe, 0);
    qk_split<<<dim3(NQ, NH), 128>>>(pKf, pKe, 1);

    // --- scores: S[h] = (Q_h @ K_h^T) / 6 ---
    mma_gemm<<<dim3(32, 32, NH), 256, MMA_SMEM>>>(
        pQe, pKe, pS, KP_HD, KP_HD, KP_HD, NQ,
        (long long)NQ * KP_HD, (long long)NQ * KP_HD, (long long)NQ * NQ,
        1.f / 6.f, nullptr, 0, 0, 0);

    // --- softmax + 2-term ext ---
    softmax_ext<<<NH * NQ, 256>>>(pS, pSe);

    // --- V projection: Vf[h] = value @ wv[h] + b[h] ---
    mma_gemm<<<dim3(7, 32, NH), 256, MMA_SMEM>>>(
        pve, pwve, pVf, KP_LD, KP_LD, KP_LD, VHD,
        0, (long long)VHD * KP_LD, (long long)NQ * VHD,
        1.f, wv_b, VHD, VHD, 0);

    // --- V^T 2-term ext [hi|hi] for ctx GEMM ---
    ext_transpose<<<dim3(128, 28, 8), dim3(32, 8)>>>(pVf, pVte, NQ, VHD, VHD, KP_MS, VHD,
                                                     (long long)NQ * VHD, (long long)VHD * KP_MS, 2, -1);

    // --- residual projection: Xf = target @ resid_w + b ---
    mma_gemm<<<dim3(28, 32, 1), 256, MMA_SMEM>>>(
        pte, pre, pXf, KP_RD, KP_RD, KP_RD, LD, 0, 0, 0, 1.f, resid_b, LD, 0, 0);

    // --- ctx: Xf[:, h*896 ..] += attn[h] @ V[h]  (2-term) ---
    mma_gemm<<<dim3(7, 32, NH), 256, MMA_SMEM>>>(
        pSe, pVte, pXf, KP_MS, KP_MS, KP_MS, LD,
        (long long)NQ * KP_MS, (long long)VHD * KP_MS, (long long)VHD,
        1.f, nullptr, 0, 0, 1);

    // --- layernorm + ext ---
    ln_ext<<<NQ, 256>>>(pXf, pXe, ln_g, ln_b);

    // --- output projection ---
    mma_gemm<<<dim3(28, 32, 1), 256, MMA_SMEM>>>(
        pXe, poe, out, KP_LD, KP_LD, KP_LD, LD, 0, 0, 0, 1.f, out_b, LD, 0, 0);
}

// round 5
// speedup vs baseline: 4.8206x; 1.1307x over previous
#include <cuda_runtime.h>
#include <cuda_bf16.h>
#include <cstdint>
#include <math.h>

// ===========================================================================
// TRAlign on mma.sync (HMMA) tensor cores — sm_103-safe baseline PTX only.
// GEMMs are bf16 with K-folded split compensation:
//   3-term: A=[hi|lo|hi] x B=[hi|hi|lo]  -> ~2^-16  (resid, out, scores, Q)
//   2-term: A=[hi|lo]    x B=[hi|hi]     -> ~2^-8, used where the error is
//           diluted (K proj, V proj, ctx)
// ===========================================================================

#define NQ 4096
#define LD 3584
#define RD 144
#define NH 4
#define HD 36
#define VHD 896

#define KP_RD   448     // 3*144 -> 448
#define KP_LD   10752   // 3*3584 (out proj)
#define KP_LD2  7168    // 2*3584 (K proj, V proj)
#define KP_HD   128     // 3*36 -> 128
#define KP_MS   8192    // 2*4096 (ctx)

// ---------------- device scratch ----------------
__device__ __align__(128) __nv_bfloat16 g_te [(size_t)NQ * KP_RD];
__device__ __align__(128) __nv_bfloat16 g_se [(size_t)NQ * KP_LD2];
__device__ __align__(128) __nv_bfloat16 g_ve [(size_t)NQ * KP_LD2];
__device__ __align__(128) __nv_bfloat16 g_wqe[(size_t)256 * KP_RD];
__device__ __align__(128) __nv_bfloat16 g_wke[(size_t)256 * KP_LD2];
__device__ __align__(128) __nv_bfloat16 g_wve[(size_t)NH * VHD * KP_LD2];
__device__ __align__(128) __nv_bfloat16 g_re [(size_t)LD * KP_RD];
__device__ __align__(128) __nv_bfloat16 g_oe [(size_t)LD * KP_LD];
__device__ __align__(128) float         g_Qf [(size_t)NQ * 256];
__device__ __align__(128) float         g_Kf [(size_t)NQ * 256];
__device__ __align__(128) __nv_bfloat16 g_Qe [(size_t)NH * NQ * KP_HD];
__device__ __align__(128) __nv_bfloat16 g_Ke [(size_t)NH * NQ * KP_HD];
__device__ __align__(128) float         g_S  [(size_t)NH * NQ * NQ];     // 268 MB
__device__ __align__(128) __nv_bfloat16 g_Se [(size_t)NH * NQ * KP_MS];
__device__ __align__(128) float         g_Vf [(size_t)NH * NQ * VHD];
__device__ __align__(128) __nv_bfloat16 g_Vte[(size_t)NH * VHD * KP_MS];
__device__ __align__(128) float         g_Xf [(size_t)NQ * LD];
__device__ __align__(128) __nv_bfloat16 g_Xe [(size_t)NQ * KP_LD];

// ---------------- PTX helpers (baseline, sm_80+) ----------------
__device__ __forceinline__ uint32_t smem_u32_of(const void* p) {
    uint32_t a;
    asm("{ .reg .u64 t; cvta.to.shared.u64 t, %1; cvt.u32.u64 %0, t; }"
        : "=r"(a) : "l"(p));
    return a;
}

__device__ __forceinline__ void cp16(uint32_t dst, const void* src) {
    asm volatile("cp.async.cg.shared.global [%0], [%1], 16;" :: "r"(dst), "l"(src));
}
__device__ __forceinline__ void cp_commit() {
    asm volatile("cp.async.commit_group;");
}
__device__ __forceinline__ void cp_wait1() {
    asm volatile("cp.async.wait_group 1;");
}

__device__ __forceinline__ void ldsm4(uint32_t* r, uint32_t addr) {
    asm volatile("ldmatrix.sync.aligned.m8n8.x4.shared.b16 {%0,%1,%2,%3}, [%4];"
                 : "=r"(r[0]), "=r"(r[1]), "=r"(r[2]), "=r"(r[3]) : "r"(addr));
}

__device__ __forceinline__ void mma16816(float* c, const uint32_t* a,
                                         uint32_t b0, uint32_t b1) {
    asm volatile(
        "mma.sync.aligned.m16n8k16.row.col.f32.bf16.bf16.f32 "
        "{%0,%1,%2,%3}, {%4,%5,%6,%7}, {%8,%9}, {%0,%1,%2,%3};"
        : "+f"(c[0]), "+f"(c[1]), "+f"(c[2]), "+f"(c[3])
        : "r"(a[0]), "r"(a[1]), "r"(a[2]), "r"(a[3]), "r"(b0), "r"(b1));
}

// ---------------- bf16 split helpers ----------------
__device__ __forceinline__ __nv_bfloat16 bf_hi(float f) { return __float2bfloat16(f); }
__device__ __forceinline__ __nv_bfloat16 bf_lo(float f) {
    float hi = __bfloat162float(__float2bfloat16(f));
    return __float2bfloat16(f - hi);
}

// ===========================================================================
// HMMA GEMM: C[M, N] = alpha * A @ B^T (+bias) (+C), optional split-K.
// A [M, K] bf16 K-major, B [N, K] bf16 K-major, (K/splitK) % 64 == 0,
// N % 128 == 0, M % 128 == 0. Tile 128x128, BK=64, 3 cp.async stages,
// 256 threads. When splitK > 1, partial results are atomicAdd-ed into a
// zeroed C (bias added only by split 0).
// ===========================================================================
#define STAGE_BYTES 36864
#define NSTAGE 3
#define MMA_SMEM (NSTAGE * STAGE_BYTES)

__device__ __forceinline__ void load_stage(uint32_t sbase,
                                           const __nv_bfloat16* A, const __nv_bfloat16* B,
                                           int lda, int ldb, int row0, int col0, int k0,
                                           int tid)
{
#pragma unroll
    for (int i = 0; i < 4; i++) {
        int c = tid + i * 256;              // 0..1023
        int r = c >> 3, cc = c & 7;         // row, 16B chunk within 64-col tile
        cp16(sbase + r * 144 + cc * 16,
             A + (size_t)(row0 + r) * lda + k0 + cc * 8);
        cp16(sbase + 18432 + r * 144 + cc * 16,
             B + (size_t)(col0 + r) * ldb + k0 + cc * 8);
    }
}

__global__ __launch_bounds__(256, 2)
void mma_gemm(const __nv_bfloat16* __restrict__ A, const __nv_bfloat16* __restrict__ B,
              float* __restrict__ C, int K, int lda, int ldb, int ldc,
              long long sA, long long sB, long long sC,
              float alpha, const float* __restrict__ bias, int biasN, long long sBias,
              int accum, int splitK)
{
    extern __shared__ char smem[];
    const uint32_t sb = smem_u32_of(smem);
    const int tid = threadIdx.x;
    const int warp = tid >> 5, lane = tid & 31;
    const int wm = warp & 1;                // M half (64 rows)
    const int wn = warp >> 1;               // N quarter (32 cols)

    const int z = blockIdx.z;
    const int batch = z / splitK;
    const int split = z - batch * splitK;
    const int Keff = K / splitK;

    A += (size_t)batch * sA + (size_t)split * Keff;
    B += (size_t)batch * sB + (size_t)split * Keff;
    C += (size_t)batch * sC;
    if (bias) bias += (size_t)batch * sBias;
    const int row0 = blockIdx.y * 128, col0 = blockIdx.x * 128;

    float acc[4][4][4];
#pragma unroll
    for (int i = 0; i < 4; i++)
#pragma unroll
        for (int j = 0; j < 4; j++)
#pragma unroll
            for (int v = 0; v < 4; v++) acc[i][j][v] = 0.f;

    const int KT = Keff >> 6;

    // prefetch NSTAGE-1 stages
#pragma unroll
    for (int s = 0; s < NSTAGE - 1; s++) {
        if (s < KT) load_stage(sb + s * STAGE_BYTES, A, B, lda, ldb, row0, col0, s * 64, tid);
        cp_commit();
    }

    const int lrow = lane & 15;             // row within 16
    const int lkof = (lane >> 4) * 16;      // byte offset for k-half (8 bf16)

    for (int kt = 0; kt < KT; kt++) {
        cp_wait1();              // stage kt group complete (this thread)
        __syncthreads();         // all threads see stage kt; oldest stage free

        int ldk = kt + NSTAGE - 1;
        if (ldk < KT)
            load_stage(sb + (ldk % NSTAGE) * STAGE_BYTES, A, B, lda, ldb, row0, col0, ldk * 64, tid);
        cp_commit();

        uint32_t abase = sb + (kt % NSTAGE) * STAGE_BYTES + (wm * 64) * 144;
        uint32_t bbase = sb + (kt % NSTAGE) * STAGE_BYTES + 18432 + (wn * 32) * 144;

#pragma unroll
        for (int k16 = 0; k16 < 4; k16++) {
            uint32_t a[4][4];
#pragma unroll
            for (int mf = 0; mf < 4; mf++)
                ldsm4(a[mf], abase + (mf * 16 + lrow) * 144 + k16 * 32 + lkof);
            uint32_t b[2][4];
#pragma unroll
            for (int nf2 = 0; nf2 < 2; nf2++)
                ldsm4(b[nf2], bbase + (nf2 * 16 + lrow) * 144 + k16 * 32 + lkof);
#pragma unroll
            for (int mf = 0; mf < 4; mf++)
#pragma unroll
                for (int nf = 0; nf < 4; nf++)
                    mma16816(acc[mf][nf], a[mf], b[nf >> 1][nf & 1], b[nf >> 1][2 + (nf & 1)]);
        }
    }

    // -------- epilogue --------
    const int qr = lane >> 2;           // 0..7
    const int qc = (lane & 3) * 2;      // 0,2,4,6
#pragma unroll
    for (int mf = 0; mf < 4; mf++) {
#pragma unroll
        for (int nf = 0; nf < 4; nf++) {
            int gr = row0 + wm * 64 + mf * 16 + qr;
            int gc = col0 + wn * 32 + nf * 8 + qc;
            float b0 = 0.f, b1 = 0.f;
            if (bias && split == 0) {
                if (gc + 0 < biasN) b0 = bias[gc + 0];
                if (gc + 1 < biasN) b1 = bias[gc + 1];
            }
#pragma unroll
            for (int h = 0; h < 2; h++) {
                int r = gr + h * 8;
                float v0 = alpha * acc[mf][nf][h * 2 + 0] + b0;
                float v1 = alpha * acc[mf][nf][h * 2 + 1] + b1;
                float* cp = C + (size_t)r * ldc + gc;
                if (splitK > 1) {
                    atomicAdd(cp + 0, v0);
                    atomicAdd(cp + 1, v1);
                } else {
                    if (accum) { v0 += cp[0]; v1 += cp[1]; }
                    float2 o = make_float2(v0, v1);
                    *(float2*)cp = o;
                }
            }
        }
    }
}

// ===========================================================================
// Conversion kernels
// ===========================================================================
// A-side row expansion: fp32 [M,Kin] -> bf16 [M,Kp], term b at cols
// [b*Kin,(b+1)*Kin): b==loIdx -> lo, else hi; zero pad beyond terms*Kin.
__global__ void ext_rows(const float* __restrict__ in, __nv_bfloat16* __restrict__ out,
                         int Kin, int ldin, int Kp, int terms, int loIdx)
{
    int c = blockIdx.x * 256 + threadIdx.x;
    if (c >= Kp) return;
    size_t row = blockIdx.y;
    int b = c / Kin;
    __nv_bfloat16 r;
    if (b >= terms) r = __float2bfloat16(0.f);
    else {
        float f = in[row * ldin + (c - b * Kin)];
        r = (b == loIdx) ? bf_lo(f) : bf_hi(f);
    }
    out[row * (size_t)Kp + c] = r;
}

// B-side transpose expansion: W fp32 [K, Nn] (ldw) -> bf16 [Np, Kp],
// out[n, b*Kin + k] = (b==loIdx ? lo : hi)(W[k, n]); rows n in [Nn,Np) zero.
__global__ void ext_transpose(const float* __restrict__ in, __nv_bfloat16* __restrict__ out,
                              int Kin, int Nn, int Np, int Kp, int ldw,
                              long long sIn, long long sOut, int terms, int loIdx)
{
    __shared__ float t[32][33];
    int b = blockIdx.z % terms, z = blockIdx.z / terms;
    in  += (size_t)z * sIn;
    out += (size_t)z * sOut;
    int k0 = blockIdx.x * 32, n0 = blockIdx.y * 32;
    int tx = threadIdx.x, ty = threadIdx.y;   // 32 x 8
#pragma unroll
    for (int i = 0; i < 4; i++) {
        int k = k0 + ty + i * 8, n = n0 + tx;
        t[ty + i * 8][tx] = (k < Kin && n < Nn) ? in[(size_t)k * ldw + n] : 0.f;
    }
    __syncthreads();
#pragma unroll
    for (int i = 0; i < 4; i++) {
        int n = n0 + ty + i * 8, k = k0 + tx;
        if (n < Np && k < Kin) {
            float f = t[tx][ty + i * 8];
            out[(size_t)n * Kp + (size_t)b * Kin + k] = (b == loIdx) ? bf_lo(f) : bf_hi(f);
        }
    }
}

// Split Q/K fp32 [4096,256] into per-head ext [H,4096,128].
// orderB=0 -> [hi|lo|hi] (A side), orderB=1 -> [hi|hi|lo] (B side).
__global__ void qk_split(const float* __restrict__ Qf, __nv_bfloat16* __restrict__ out, int orderB)
{
    int h = blockIdx.y, row = blockIdx.x, c = threadIdx.x;   // 128 threads
    const float* src = Qf + (size_t)row * 256 + h * HD;
    __nv_bfloat16 o;
    if (c >= 3 * HD) o = __float2bfloat16(0.f);
    else {
        int b = c / HD;
        float f = src[c - b * HD];
        bool isLo = orderB ? (b == 2) : (b == 1);
        o = isLo ? bf_lo(f) : bf_hi(f);
    }
    out[((size_t)h * NQ + row) * KP_HD + c] = o;
}

// Softmax (row of 4096) fused with A-side 2-term ext write [hi|lo] into [*,8192].
__global__ __launch_bounds__(256)
void softmax_ext(const float* __restrict__ S, __nv_bfloat16* __restrict__ out)
{
    const float* p = S + (size_t)blockIdx.x * 4096;
    __nv_bfloat16* q = out + (size_t)blockIdx.x * KP_MS;
    const int t = threadIdx.x;
    float v[16];
    float mx = -1e30f;
#pragma unroll
    for (int i = 0; i < 16; i++) { v[i] = p[t + i * 256]; mx = fmaxf(mx, v[i]); }
    __shared__ float red[256];
    red[t] = mx; __syncthreads();
#pragma unroll
    for (int s = 128; s > 0; s >>= 1) { if (t < s) red[t] = fmaxf(red[t], red[t + s]); __syncthreads(); }
    mx = red[0]; __syncthreads();
    float sum = 0.f;
#pragma unroll
    for (int i = 0; i < 16; i++) { v[i] = __expf(v[i] - mx); sum += v[i]; }
    red[t] = sum; __syncthreads();
#pragma unroll
    for (int s = 128; s > 0; s >>= 1) { if (t < s) red[t] += red[t + s]; __syncthreads(); }
    const float inv = 1.f / red[0];
#pragma unroll
    for (int i = 0; i < 16; i++) {
        int c = t + i * 256;
        float pv = v[i] * inv;
        __nv_bfloat16 hi = __float2bfloat16(pv);
        q[c] = hi;
        q[4096 + c] = __float2bfloat16(pv - __bfloat162float(hi));
    }
}

// LayerNorm (row of 3584) fused with A-side 3-term ext write into [*,10752].
__global__ __launch_bounds__(256)
void ln_ext(const float* __restrict__ X, __nv_bfloat16* __restrict__ out,
            const float* __restrict__ g, const float* __restrict__ b)
{
    const int D = LD;   // 3584 = 14*256
    const float* p = X + (size_t)blockIdx.x * D;
    __nv_bfloat16* q = out + (size_t)blockIdx.x * KP_LD;
    const int t = threadIdx.x;
    float v[14];
    float s = 0.f;
#pragma unroll
    for (int i = 0; i < 14; i++) { v[i] = p[t + i * 256]; s += v[i]; }
    __shared__ float red[256];
    red[t] = s; __syncthreads();
#pragma unroll
    for (int st = 128; st > 0; st >>= 1) { if (t < st) red[t] += red[t + st]; __syncthreads(); }
    const float mean = red[0] / (float)D; __syncthreads();
    float sq = 0.f;
#pragma unroll
    for (int i = 0; i < 14; i++) { float d = v[i] - mean; sq += d * d; }
    red[t] = sq; __syncthreads();
#pragma unroll
    for (int st = 128; st > 0; st >>= 1) { if (t < st) red[t] += red[t + st]; __syncthreads(); }
    const float inv = rsqrtf(red[0] / (float)D + 1e-5f);
#pragma unroll
    for (int i = 0; i < 14; i++) {
        int c = t + i * 256;
        float y = (v[i] - mean) * inv * g[c] + b[c];
        __nv_bfloat16 hi = __float2bfloat16(y);
        q[c] = hi;
        q[7168 + c] = hi;
        q[3584 + c] = __float2bfloat16(y - __bfloat162float(hi));
    }
}

// ===========================================================================
// Launcher
// ===========================================================================
extern "C" void kernel_launch(void* const* d_in, const int* in_sizes, int n_in,
                              void* d_out, int out_size)
{
    const float* target  = (const float*)d_in[0];
    const float* source  = (const float*)d_in[1];
    const float* value   = (const float*)d_in[2];
    const float* wq_w    = (const float*)d_in[3];
    const float* wq_b    = (const float*)d_in[4];
    const float* wk_w    = (const float*)d_in[5];
    const float* wk_b    = (const float*)d_in[6];
    const float* wv_w    = (const float*)d_in[7];
    const float* wv_b    = (const float*)d_in[8];
    const float* resid_w = (const float*)d_in[9];
    const float* resid_b = (const float*)d_in[10];
    const float* out_w   = (const float*)d_in[11];
    const float* out_b   = (const float*)d_in[12];
    const float* ln_g    = (const float*)d_in[13];
    const float* ln_b    = (const float*)d_in[14];
    float* out = (float*)d_out;

    __nv_bfloat16 *pte, *pse, *pve, *pwqe, *pwke, *pwve, *pre, *poe;
    __nv_bfloat16 *pQe, *pKe, *pSe, *pVte, *pXe;
    float *pQf, *pKf, *pS, *pVf, *pXf;
    cudaGetSymbolAddress((void**)&pte, g_te);
    cudaGetSymbolAddress((void**)&pse, g_se);
    cudaGetSymbolAddress((void**)&pve, g_ve);
    cudaGetSymbolAddress((void**)&pwqe, g_wqe);
    cudaGetSymbolAddress((void**)&pwke, g_wke);
    cudaGetSymbolAddress((void**)&pwve, g_wve);
    cudaGetSymbolAddress((void**)&pre, g_re);
    cudaGetSymbolAddress((void**)&poe, g_oe);
    cudaGetSymbolAddress((void**)&pQf, g_Qf);
    cudaGetSymbolAddress((void**)&pKf, g_Kf);
    cudaGetSymbolAddress((void**)&pQe, g_Qe);
    cudaGetSymbolAddress((void**)&pKe, g_Ke);
    cudaGetSymbolAddress((void**)&pS, g_S);
    cudaGetSymbolAddress((void**)&pSe, g_Se);
    cudaGetSymbolAddress((void**)&pVf, g_Vf);
    cudaGetSymbolAddress((void**)&pVte, g_Vte);
    cudaGetSymbolAddress((void**)&pXf, g_Xf);
    cudaGetSymbolAddress((void**)&pXe, g_Xe);

    cudaFuncSetAttribute(mma_gemm, cudaFuncAttributeMaxDynamicSharedMemorySize, MMA_SMEM);

    // zero pads / split-K accumulators
    cudaMemsetAsync(pwqe, 0, (size_t)256 * KP_RD * sizeof(__nv_bfloat16));
    cudaMemsetAsync(pre, 0, (size_t)LD * KP_RD * sizeof(__nv_bfloat16));
    cudaMemsetAsync(pKf, 0, (size_t)NQ * 256 * sizeof(float));

    // --- operand expansions ---
    ext_rows<<<dim3(2, NQ), 256>>>(target, pte, RD, RD, KP_RD, 3, 1);
    ext_rows<<<dim3(28, NQ), 256>>>(source, pse, LD, LD, KP_LD2, 2, 1);
    ext_rows<<<dim3(28, NQ), 256>>>(value, pve, LD, LD, KP_LD2, 2, 1);

    ext_transpose<<<dim3(5, 8, 3), dim3(32, 8)>>>(wq_w, pwqe, RD, RD, 256, KP_RD, RD, 0, 0, 3, 2);
    ext_transpose<<<dim3(112, 8, 2), dim3(32, 8)>>>(wk_w, pwke, LD, RD, 256, KP_LD2, RD, 0, 0, 2, -1);
    ext_transpose<<<dim3(112, 28, 8), dim3(32, 8)>>>(wv_w, pwve, LD, VHD, VHD, KP_LD2, VHD,
                                                     (long long)LD * VHD, (long long)VHD * KP_LD2, 2, -1);
    ext_transpose<<<dim3(5, 112, 3), dim3(32, 8)>>>(resid_w, pre, RD, LD, LD, KP_RD, LD, 0, 0, 3, 2);
    ext_transpose<<<dim3(112, 112, 3), dim3(32, 8)>>>(out_w, poe, LD, LD, LD, KP_LD, LD, 0, 0, 3, 2);

    // --- Q projection (3-term, small) ---
    mma_gemm<<<dim3(2, 32, 1), 256, MMA_SMEM>>>(
        pte, pwqe, pQf, KP_RD, KP_RD, KP_RD, 256, 0, 0, 0, 1.f, wq_b, RD, 0, 0, 1);
    // --- K projection (2-term, split-K=4 into zeroed Kf) ---
    mma_gemm<<<dim3(2, 32, 4), 256, MMA_SMEM>>>(
        pse, pwke, pKf, KP_LD2, KP_LD2, KP_LD2, 256, 0, 0, 0, 1.f, wk_b, RD, 0, 0, 4);
    qk_split<<<dim3(NQ, NH), 128>>>(pQf, pQe, 0);
    qk_split<<<dim3(NQ, NH), 128>>>(pKf, pKe, 1);

    // --- scores: S[h] = (Q_h @ K_h^T) / 6 ---
    mma_gemm<<<dim3(32, 32, NH), 256, MMA_SMEM>>>(
        pQe, pKe, pS, KP_HD, KP_HD, KP_HD, NQ,
        (long long)NQ * KP_HD, (long long)NQ * KP_HD, (long long)NQ * NQ,
        1.f / 6.f, nullptr, 0, 0, 0, 1);

    // --- softmax + 2-term ext ---
    softmax_ext<<<NH * NQ, 256>>>(pS, pSe);

    // --- V projection (2-term): Vf[h] = value @ wv[h] + b[h] ---
    mma_gemm<<<dim3(7, 32, NH), 256, MMA_SMEM>>>(
        pve, pwve, pVf, KP_LD2, KP_LD2, KP_LD2, VHD,
        0, (long long)VHD * KP_LD2, (long long)NQ * VHD,
        1.f, wv_b, VHD, VHD, 0, 1);

    // --- V^T 2-term ext [hi|hi] for ctx GEMM ---
    ext_transpose<<<dim3(128, 28, 8), dim3(32, 8)>>>(pVf, pVte, NQ, VHD, VHD, KP_MS, VHD,
                                                     (long long)NQ * VHD, (long long)VHD * KP_MS, 2, -1);

    // --- residual projection: Xf = target @ resid_w + b (3-term) ---
    mma_gemm<<<dim3(28, 32, 1), 256, MMA_SMEM>>>(
        pte, pre, pXf, KP_RD, KP_RD, KP_RD, LD, 0, 0, 0, 1.f, resid_b, LD, 0, 0, 1);

    // --- ctx: Xf[:, h*896 ..] += attn[h] @ V[h]  (2-term) ---
    mma_gemm<<<dim3(7, 32, NH), 256, MMA_SMEM>>>(
        pSe, pVte, pXf, KP_MS, KP_MS, KP_MS, LD,
        (long long)NQ * KP_MS, (long long)VHD * KP_MS, (long long)VHD,
        1.f, nullptr, 0, 0, 1, 1);

    // --- layernorm + 3-term ext ---
    ln_ext<<<NQ, 256>>>(pXf, pXe, ln_g, ln_b);

    // --- output projection (3-term) ---
    mma_gemm<<<dim3(28, 32, 1), 256, MMA_SMEM>>>(
        pXe, poe, out, KP_LD, KP_LD, KP_LD, LD, 0, 0, 0, 1.f, out_b, LD, 0, 0, 1);
}

// round 6
// speedup vs baseline: 6.7663x; 1.4036x over previous
#include <cuda_runtime.h>
#include <cuda_bf16.h>
#include <cstdint>
#include <math.h>

// ===========================================================================
// TRAlign on mma.sync (HMMA) tensor cores — sm_103-safe baseline PTX only.
// Precision plan (error contributions to final output, vs 1e-3 gate):
//   resid/out/Q proj : 3-term split  A=[hi|lo|hi] x B=[hi|hi|lo]  (~2^-16)
//   K proj, scores   : 1-term bf16   (scores tiny -> ~2e-5 after softmax)
//   V proj, ctx      : 1-term bf16   (ctx/x dilution ~0.08 -> ~1.5e-4 each)
//   S stored bf16, softmax in-place  (~4e-5)
// ===========================================================================

#define NQ 4096
#define LD 3584
#define RD 144
#define NH 4
#define HD 36
#define VHD 896

#define KP_RD   448     // 3*144 -> 448  (Q proj, resid proj)
#define KP_LD   10752   // 3*3584        (out proj)
#define KP_HD   64      // 36 -> 64      (scores, 1-term)

// ---------------- device scratch ----------------
__device__ __align__(128) __nv_bfloat16 g_te [(size_t)NQ * KP_RD];
__device__ __align__(128) __nv_bfloat16 g_se [(size_t)NQ * LD];          // source bf16
__device__ __align__(128) __nv_bfloat16 g_ve [(size_t)NQ * LD];          // value bf16
__device__ __align__(128) __nv_bfloat16 g_wqe[(size_t)256 * KP_RD];
__device__ __align__(128) __nv_bfloat16 g_wke[(size_t)256 * LD];         // wk^T bf16
__device__ __align__(128) __nv_bfloat16 g_wve[(size_t)NH * VHD * LD];    // wv^T bf16
__device__ __align__(128) __nv_bfloat16 g_re [(size_t)LD * KP_RD];
__device__ __align__(128) __nv_bfloat16 g_oe [(size_t)LD * KP_LD];
__device__ __align__(128) float         g_Qf [(size_t)NQ * 256];
__device__ __align__(128) float         g_Kf [(size_t)NQ * 256];
__device__ __align__(128) __nv_bfloat16 g_Qe [(size_t)NH * NQ * KP_HD];
__device__ __align__(128) __nv_bfloat16 g_Ke [(size_t)NH * NQ * KP_HD];
__device__ __align__(128) __nv_bfloat16 g_S  [(size_t)NH * NQ * NQ];     // scores/attn bf16 (134 MB)
__device__ __align__(128) float         g_Vf [(size_t)NH * NQ * VHD];
__device__ __align__(128) __nv_bfloat16 g_Vte[(size_t)NH * VHD * NQ];    // V^T bf16
__device__ __align__(128) float         g_Xf [(size_t)NQ * LD];
__device__ __align__(128) __nv_bfloat16 g_Xe [(size_t)NQ * KP_LD];

// ---------------- PTX helpers (baseline, sm_80+) ----------------
__device__ __forceinline__ uint32_t smem_u32_of(const void* p) {
    uint32_t a;
    asm("{ .reg .u64 t; cvta.to.shared.u64 t, %1; cvt.u32.u64 %0, t; }"
        : "=r"(a) : "l"(p));
    return a;
}

__device__ __forceinline__ void cp16(uint32_t dst, const void* src) {
    asm volatile("cp.async.cg.shared.global [%0], [%1], 16;" :: "r"(dst), "l"(src));
}
__device__ __forceinline__ void cp_commit() {
    asm volatile("cp.async.commit_group;");
}
__device__ __forceinline__ void cp_wait1() {
    asm volatile("cp.async.wait_group 1;");
}

__device__ __forceinline__ void ldsm4(uint32_t* r, uint32_t addr) {
    asm volatile("ldmatrix.sync.aligned.m8n8.x4.shared.b16 {%0,%1,%2,%3}, [%4];"
                 : "=r"(r[0]), "=r"(r[1]), "=r"(r[2]), "=r"(r[3]) : "r"(addr));
}

__device__ __forceinline__ void mma16816(float* c, const uint32_t* a,
                                         uint32_t b0, uint32_t b1) {
    asm volatile(
        "mma.sync.aligned.m16n8k16.row.col.f32.bf16.bf16.f32 "
        "{%0,%1,%2,%3}, {%4,%5,%6,%7}, {%8,%9}, {%0,%1,%2,%3};"
        : "+f"(c[0]), "+f"(c[1]), "+f"(c[2]), "+f"(c[3])
        : "r"(a[0]), "r"(a[1]), "r"(a[2]), "r"(a[3]), "r"(b0), "r"(b1));
}

// ---------------- bf16 split helpers ----------------
__device__ __forceinline__ __nv_bfloat16 bf_hi(float f) { return __float2bfloat16(f); }
__device__ __forceinline__ __nv_bfloat16 bf_lo(float f) {
    float hi = __bfloat162float(__float2bfloat16(f));
    return __float2bfloat16(f - hi);
}

// ===========================================================================
// HMMA GEMM: C[M, N] = alpha * A @ B^T (+bias) (+C), optional split-K,
// optional bf16 output. A [M, K] bf16 K-major, B [N, K] bf16 K-major,
// (K/splitK) % 64 == 0, N % 128 == 0, M % 128 == 0.
// Tile 128x128, BK=64, 3 cp.async stages, 256 threads.
// ===========================================================================
#define STAGE_BYTES 36864
#define NSTAGE 3
#define MMA_SMEM (NSTAGE * STAGE_BYTES)

__device__ __forceinline__ void load_stage(uint32_t sbase,
                                           const __nv_bfloat16* A, const __nv_bfloat16* B,
                                           int lda, int ldb, int row0, int col0, int k0,
                                           int tid)
{
#pragma unroll
    for (int i = 0; i < 4; i++) {
        int c = tid + i * 256;              // 0..1023
        int r = c >> 3, cc = c & 7;         // row, 16B chunk within 64-col tile
        cp16(sbase + r * 144 + cc * 16,
             A + (size_t)(row0 + r) * lda + k0 + cc * 8);
        cp16(sbase + 18432 + r * 144 + cc * 16,
             B + (size_t)(col0 + r) * ldb + k0 + cc * 8);
    }
}

__global__ __launch_bounds__(256, 2)
void mma_gemm(const __nv_bfloat16* __restrict__ A, const __nv_bfloat16* __restrict__ B,
              void* __restrict__ Cv, int K, int lda, int ldb, int ldc,
              long long sA, long long sB, long long sC,
              float alpha, const float* __restrict__ bias, int biasN, long long sBias,
              int accum, int splitK, int outBf16)
{
    extern __shared__ char smem[];
    const uint32_t sb = smem_u32_of(smem);
    const int tid = threadIdx.x;
    const int warp = tid >> 5, lane = tid & 31;
    const int wm = warp & 1;                // M half (64 rows)
    const int wn = warp >> 1;               // N quarter (32 cols)

    const int z = blockIdx.z;
    const int batch = z / splitK;
    const int split = z - batch * splitK;
    const int Keff = K / splitK;

    A += (size_t)batch * sA + (size_t)split * Keff;
    B += (size_t)batch * sB + (size_t)split * Keff;
    float* Cf = (float*)Cv + (size_t)batch * sC;
    __nv_bfloat16* Cb = (__nv_bfloat16*)Cv + (size_t)batch * sC;
    if (bias) bias += (size_t)batch * sBias;
    const int row0 = blockIdx.y * 128, col0 = blockIdx.x * 128;

    float acc[4][4][4];
#pragma unroll
    for (int i = 0; i < 4; i++)
#pragma unroll
        for (int j = 0; j < 4; j++)
#pragma unroll
            for (int v = 0; v < 4; v++) acc[i][j][v] = 0.f;

    const int KT = Keff >> 6;

    // prefetch NSTAGE-1 stages
#pragma unroll
    for (int s = 0; s < NSTAGE - 1; s++) {
        if (s < KT) load_stage(sb + s * STAGE_BYTES, A, B, lda, ldb, row0, col0, s * 64, tid);
        cp_commit();
    }

    const int lrow = lane & 15;             // row within 16
    const int lkof = (lane >> 4) * 16;      // byte offset for k-half (8 bf16)

    for (int kt = 0; kt < KT; kt++) {
        cp_wait1();              // stage kt group complete (this thread)
        __syncthreads();         // all threads see stage kt; oldest stage free

        int ldk = kt + NSTAGE - 1;
        if (ldk < KT)
            load_stage(sb + (ldk % NSTAGE) * STAGE_BYTES, A, B, lda, ldb, row0, col0, ldk * 64, tid);
        cp_commit();

        uint32_t abase = sb + (kt % NSTAGE) * STAGE_BYTES + (wm * 64) * 144;
        uint32_t bbase = sb + (kt % NSTAGE) * STAGE_BYTES + 18432 + (wn * 32) * 144;

#pragma unroll
        for (int k16 = 0; k16 < 4; k16++) {
            uint32_t a[4][4];
#pragma unroll
            for (int mf = 0; mf < 4; mf++)
                ldsm4(a[mf], abase + (mf * 16 + lrow) * 144 + k16 * 32 + lkof);
            uint32_t b[2][4];
#pragma unroll
            for (int nf2 = 0; nf2 < 2; nf2++)
                ldsm4(b[nf2], bbase + (nf2 * 16 + lrow) * 144 + k16 * 32 + lkof);
#pragma unroll
            for (int mf = 0; mf < 4; mf++)
#pragma unroll
                for (int nf = 0; nf < 4; nf++)
                    mma16816(acc[mf][nf], a[mf], b[nf >> 1][nf & 1], b[nf >> 1][2 + (nf & 1)]);
        }
    }

    // -------- epilogue --------
    const int qr = lane >> 2;           // 0..7
    const int qc = (lane & 3) * 2;      // 0,2,4,6
#pragma unroll
    for (int mf = 0; mf < 4; mf++) {
#pragma unroll
        for (int nf = 0; nf < 4; nf++) {
            int gr = row0 + wm * 64 + mf * 16 + qr;
            int gc = col0 + wn * 32 + nf * 8 + qc;
            float b0 = 0.f, b1 = 0.f;
            if (bias && split == 0) {
                if (gc + 0 < biasN) b0 = bias[gc + 0];
                if (gc + 1 < biasN) b1 = bias[gc + 1];
            }
#pragma unroll
            for (int h = 0; h < 2; h++) {
                int r = gr + h * 8;
                float v0 = alpha * acc[mf][nf][h * 2 + 0] + b0;
                float v1 = alpha * acc[mf][nf][h * 2 + 1] + b1;
                if (outBf16) {
                    __nv_bfloat162 o;
                    o.x = __float2bfloat16(v0);
                    o.y = __float2bfloat16(v1);
                    *(__nv_bfloat162*)(Cb + (size_t)r * ldc + gc) = o;
                } else {
                    float* cp = Cf + (size_t)r * ldc + gc;
                    if (splitK > 1) {
                        atomicAdd(cp + 0, v0);
                        atomicAdd(cp + 1, v1);
                    } else {
                        if (accum) { v0 += cp[0]; v1 += cp[1]; }
                        float2 o = make_float2(v0, v1);
                        *(float2*)cp = o;
                    }
                }
            }
        }
    }
}

// ===========================================================================
// Conversion kernels
// ===========================================================================
// A-side row expansion: fp32 [M,Kin] -> bf16 [M,Kp], term b at cols
// [b*Kin,(b+1)*Kin): b==loIdx -> lo, else hi; zero pad beyond terms*Kin.
__global__ void ext_rows(const float* __restrict__ in, __nv_bfloat16* __restrict__ out,
                         int Kin, int ldin, int Kp, int terms, int loIdx)
{
    int c = blockIdx.x * 256 + threadIdx.x;
    if (c >= Kp) return;
    size_t row = blockIdx.y;
    int b = c / Kin;
    __nv_bfloat16 r;
    if (b >= terms) r = __float2bfloat16(0.f);
    else {
        float f = in[row * ldin + (c - b * Kin)];
        r = (b == loIdx) ? bf_lo(f) : bf_hi(f);
    }
    out[row * (size_t)Kp + c] = r;
}

// B-side transpose expansion: W fp32 [K, Nn] (ldw) -> bf16 [Np, Kp],
// out[n, b*Kin + k] = (b==loIdx ? lo : hi)(W[k, n]); rows n in [Nn,Np) zero.
__global__ void ext_transpose(const float* __restrict__ in, __nv_bfloat16* __restrict__ out,
                              int Kin, int Nn, int Np, int Kp, int ldw,
                              long long sIn, long long sOut, int terms, int loIdx)
{
    __shared__ float t[32][33];
    int b = blockIdx.z % terms, z = blockIdx.z / terms;
    in  += (size_t)z * sIn;
    out += (size_t)z * sOut;
    int k0 = blockIdx.x * 32, n0 = blockIdx.y * 32;
    int tx = threadIdx.x, ty = threadIdx.y;   // 32 x 8
#pragma unroll
    for (int i = 0; i < 4; i++) {
        int k = k0 + ty + i * 8, n = n0 + tx;
        t[ty + i * 8][tx] = (k < Kin && n < Nn) ? in[(size_t)k * ldw + n] : 0.f;
    }
    __syncthreads();
#pragma unroll
    for (int i = 0; i < 4; i++) {
        int n = n0 + ty + i * 8, k = k0 + tx;
        if (n < Np && k < Kin) {
            float f = t[tx][ty + i * 8];
            out[(size_t)n * Kp + (size_t)b * Kin + k] = (b == loIdx) ? bf_lo(f) : bf_hi(f);
        }
    }
}

// Split Q/K fp32 [4096,256] into per-head bf16 [H,4096,64] (cols >= 36 zero).
__global__ void qk_split(const float* __restrict__ Qf, __nv_bfloat16* __restrict__ out)
{
    int h = blockIdx.y, row = blockIdx.x, c = threadIdx.x;   // 64 threads
    const float* src = Qf + (size_t)row * 256 + h * HD;
    out[((size_t)h * NQ + row) * KP_HD + c] =
        (c < HD) ? bf_hi(src[c]) : __float2bfloat16(0.f);
}

// Softmax over bf16 row of 4096, in place (attn written as bf16 hi).
__global__ __launch_bounds__(256)
void softmax_ext(__nv_bfloat16* __restrict__ S)
{
    __nv_bfloat16* p = S + (size_t)blockIdx.x * 4096;
    const int t = threadIdx.x;
    float v[16];
    float mx = -1e30f;
#pragma unroll
    for (int i = 0; i < 16; i++) {
        v[i] = __bfloat162float(p[t + i * 256]);
        mx = fmaxf(mx, v[i]);
    }
    __shared__ float red[256];
    red[t] = mx; __syncthreads();
#pragma unroll
    for (int s = 128; s > 0; s >>= 1) { if (t < s) red[t] = fmaxf(red[t], red[t + s]); __syncthreads(); }
    mx = red[0]; __syncthreads();
    float sum = 0.f;
#pragma unroll
    for (int i = 0; i < 16; i++) { v[i] = __expf(v[i] - mx); sum += v[i]; }
    red[t] = sum; __syncthreads();
#pragma unroll
    for (int s = 128; s > 0; s >>= 1) { if (t < s) red[t] += red[t + s]; __syncthreads(); }
    const float inv = 1.f / red[0];
#pragma unroll
    for (int i = 0; i < 16; i++)
        p[t + i * 256] = __float2bfloat16(v[i] * inv);
}

// LayerNorm (row of 3584) fused with A-side 3-term ext write into [*,10752].
__global__ __launch_bounds__(256)
void ln_ext(const float* __restrict__ X, __nv_bfloat16* __restrict__ out,
            const float* __restrict__ g, const float* __restrict__ b)
{
    const int D = LD;   // 3584 = 14*256
    const float* p = X + (size_t)blockIdx.x * D;
    __nv_bfloat16* q = out + (size_t)blockIdx.x * KP_LD;
    const int t = threadIdx.x;
    float v[14];
    float s = 0.f;
#pragma unroll
    for (int i = 0; i < 14; i++) { v[i] = p[t + i * 256]; s += v[i]; }
    __shared__ float red[256];
    red[t] = s; __syncthreads();
#pragma unroll
    for (int st = 128; st > 0; st >>= 1) { if (t < st) red[t] += red[t + st]; __syncthreads(); }
    const float mean = red[0] / (float)D; __syncthreads();
    float sq = 0.f;
#pragma unroll
    for (int i = 0; i < 14; i++) { float d = v[i] - mean; sq += d * d; }
    red[t] = sq; __syncthreads();
#pragma unroll
    for (int st = 128; st > 0; st >>= 1) { if (t < st) red[t] += red[t + st]; __syncthreads(); }
    const float inv = rsqrtf(red[0] / (float)D + 1e-5f);
#pragma unroll
    for (int i = 0; i < 14; i++) {
        int c = t + i * 256;
        float y = (v[i] - mean) * inv * g[c] + b[c];
        __nv_bfloat16 hi = __float2bfloat16(y);
        q[c] = hi;
        q[7168 + c] = hi;
        q[3584 + c] = __float2bfloat16(y - __bfloat162float(hi));
    }
}

// ===========================================================================
// Launcher
// ===========================================================================
extern "C" void kernel_launch(void* const* d_in, const int* in_sizes, int n_in,
                              void* d_out, int out_size)
{
    const float* target  = (const float*)d_in[0];
    const float* source  = (const float*)d_in[1];
    const float* value   = (const float*)d_in[2];
    const float* wq_w    = (const float*)d_in[3];
    const float* wq_b    = (const float*)d_in[4];
    const float* wk_w    = (const float*)d_in[5];
    const float* wk_b    = (const float*)d_in[6];
    const float* wv_w    = (const float*)d_in[7];
    const float* wv_b    = (const float*)d_in[8];
    const float* resid_w = (const float*)d_in[9];
    const float* resid_b = (const float*)d_in[10];
    const float* out_w   = (const float*)d_in[11];
    const float* out_b   = (const float*)d_in[12];
    const float* ln_g    = (const float*)d_in[13];
    const float* ln_b    = (const float*)d_in[14];
    float* out = (float*)d_out;

    __nv_bfloat16 *pte, *pse, *pve, *pwqe, *pwke, *pwve, *pre, *poe;
    __nv_bfloat16 *pQe, *pKe, *pS, *pVte, *pXe;
    float *pQf, *pKf, *pVf, *pXf;
    cudaGetSymbolAddress((void**)&pte, g_te);
    cudaGetSymbolAddress((void**)&pse, g_se);
    cudaGetSymbolAddress((void**)&pve, g_ve);
    cudaGetSymbolAddress((void**)&pwqe, g_wqe);
    cudaGetSymbolAddress((void**)&pwke, g_wke);
    cudaGetSymbolAddress((void**)&pwve, g_wve);
    cudaGetSymbolAddress((void**)&pre, g_re);
    cudaGetSymbolAddress((void**)&poe, g_oe);
    cudaGetSymbolAddress((void**)&pQf, g_Qf);
    cudaGetSymbolAddress((void**)&pKf, g_Kf);
    cudaGetSymbolAddress((void**)&pQe, g_Qe);
    cudaGetSymbolAddress((void**)&pKe, g_Ke);
    cudaGetSymbolAddress((void**)&pS, g_S);
    cudaGetSymbolAddress((void**)&pVf, g_Vf);
    cudaGetSymbolAddress((void**)&pVte, g_Vte);
    cudaGetSymbolAddress((void**)&pXf, g_Xf);
    cudaGetSymbolAddress((void**)&pXe, g_Xe);

    cudaFuncSetAttribute(mma_gemm, cudaFuncAttributeMaxDynamicSharedMemorySize, MMA_SMEM);

    // zero pads / split-K accumulators
    cudaMemsetAsync(pwqe, 0, (size_t)256 * KP_RD * sizeof(__nv_bfloat16));
    cudaMemsetAsync(pre, 0, (size_t)LD * KP_RD * sizeof(__nv_bfloat16));
    cudaMemsetAsync(pKf, 0, (size_t)NQ * 256 * sizeof(float));

    // --- operand conversions ---
    ext_rows<<<dim3(2, NQ), 256>>>(target, pte, RD, RD, KP_RD, 3, 1);
    ext_rows<<<dim3(14, NQ), 256>>>(source, pse, LD, LD, LD, 1, -1);
    ext_rows<<<dim3(14, NQ), 256>>>(value, pve, LD, LD, LD, 1, -1);

    ext_transpose<<<dim3(5, 8, 3), dim3(32, 8)>>>(wq_w, pwqe, RD, RD, 256, KP_RD, RD, 0, 0, 3, 2);
    ext_transpose<<<dim3(112, 8, 1), dim3(32, 8)>>>(wk_w, pwke, LD, RD, 256, LD, RD, 0, 0, 1, -1);
    ext_transpose<<<dim3(112, 28, 4), dim3(32, 8)>>>(wv_w, pwve, LD, VHD, VHD, LD, VHD,
                                                     (long long)LD * VHD, (long long)VHD * LD, 1, -1);
    ext_transpose<<<dim3(5, 112, 3), dim3(32, 8)>>>(resid_w, pre, RD, LD, LD, KP_RD, LD, 0, 0, 3, 2);
    ext_transpose<<<dim3(112, 112, 3), dim3(32, 8)>>>(out_w, poe, LD, LD, LD, KP_LD, LD, 0, 0, 3, 2);

    // --- Q projection (3-term) ---
    mma_gemm<<<dim3(2, 32, 1), 256, MMA_SMEM>>>(
        pte, pwqe, pQf, KP_RD, KP_RD, KP_RD, 256, 0, 0, 0, 1.f, wq_b, RD, 0, 0, 1, 0);
    // --- K projection (1-term, split-K=4 into zeroed Kf) ---
    mma_gemm<<<dim3(2, 32, 4), 256, MMA_SMEM>>>(
        pse, pwke, pKf, LD, LD, LD, 256, 0, 0, 0, 1.f, wk_b, RD, 0, 0, 4, 0);
    qk_split<<<dim3(NQ, NH), KP_HD>>>(pQf, pQe);
    qk_split<<<dim3(NQ, NH), KP_HD>>>(pKf, pKe);

    // --- scores: S[h] = (Q_h @ K_h^T) / 6, bf16 output ---
    mma_gemm<<<dim3(32, 32, NH), 256, MMA_SMEM>>>(
        pQe, pKe, pS, KP_HD, KP_HD, KP_HD, NQ,
        (long long)NQ * KP_HD, (long long)NQ * KP_HD, (long long)NQ * NQ,
        1.f / 6.f, nullptr, 0, 0, 0, 1, 1);

    // --- softmax in place (bf16 attn) ---
    softmax_ext<<<NH * NQ, 256>>>(pS);

    // --- V projection (1-term): Vf[h] = value @ wv[h] + b[h] ---
    mma_gemm<<<dim3(7, 32, NH), 256, MMA_SMEM>>>(
        pve, pwve, pVf, LD, LD, LD, VHD,
        0, (long long)VHD * LD, (long long)NQ * VHD,
        1.f, wv_b, VHD, VHD, 0, 1, 0);

    // --- V^T bf16 for ctx GEMM ---
    ext_transpose<<<dim3(128, 28, 4), dim3(32, 8)>>>(pVf, pVte, NQ, VHD, VHD, NQ, VHD,
                                                     (long long)NQ * VHD, (long long)VHD * NQ, 1, -1);

    // --- residual projection: Xf = target @ resid_w + b (3-term) ---
    mma_gemm<<<dim3(28, 32, 1), 256, MMA_SMEM>>>(
        pte, pre, pXf, KP_RD, KP_RD, KP_RD, LD, 0, 0, 0, 1.f, resid_b, LD, 0, 0, 1, 0);

    // --- ctx: Xf[:, h*896 ..] += attn[h] @ V[h]  (1-term) ---
    mma_gemm<<<dim3(7, 32, NH), 256, MMA_SMEM>>>(
        pS, pVte, pXf, NQ, NQ, NQ, LD,
        (long long)NQ * NQ, (long long)VHD * NQ, (long long)VHD,
        1.f, nullptr, 0, 0, 1, 1, 0);

    // --- layernorm + 3-term ext ---
    ln_ext<<<NQ, 256>>>(pXf, pXe, ln_g, ln_b);

    // --- output projection (3-term) ---
    mma_gemm<<<dim3(28, 32, 1), 256, MMA_SMEM>>>(
        pXe, poe, out, KP_LD, KP_LD, KP_LD, LD, 0, 0, 0, 1.f, out_b, LD, 0, 0, 1, 0);
}

// round 7
// speedup vs baseline: 8.0986x; 1.1969x over previous
#include <cuda_runtime.h>
#include <cuda_fp16.h>
#include <cstdint>
#include <math.h>

// ===========================================================================
// TRAlign on mma.sync (HMMA) tensor cores — sm_103-safe baseline PTX only.
// All GEMMs in fp16 (11-bit mantissa) with K-folded split compensation:
//   2-term: A=[hi|lo] x B=[hi|hi]  -> missing A*B_lo ~2^-12  (Q/resid/out)
//   1-term: plain fp16             -> ~2^-11                (K, scores, V, ctx)
// fp32 accumulate everywhere (mma .f32.f16.f16.f32).
// ===========================================================================

#define NQ 4096
#define LD 3584
#define RD 144
#define NH 4
#define HD 36
#define VHD 896

#define KP_RD   320     // 2*144 = 288 -> 320  (Q proj, resid proj)
#define KP_LD2  7168    // 2*3584              (out proj)
#define KP_HD   64      // 36 -> 64            (scores, 1-term)

// ---------------- device scratch ----------------
__device__ __align__(128) __half g_te [(size_t)NQ * KP_RD];
__device__ __align__(128) __half g_se [(size_t)NQ * LD];          // source fp16
__device__ __align__(128) __half g_ve [(size_t)NQ * LD];          // value fp16
__device__ __align__(128) __half g_wqe[(size_t)256 * KP_RD];
__device__ __align__(128) __half g_wke[(size_t)256 * LD];         // wk^T fp16
__device__ __align__(128) __half g_wve[(size_t)NH * VHD * LD];    // wv^T fp16
__device__ __align__(128) __half g_re [(size_t)LD * KP_RD];
__device__ __align__(128) __half g_oe [(size_t)LD * KP_LD2];
__device__ __align__(128) float  g_Qf [(size_t)NQ * 256];
__device__ __align__(128) float  g_Kf [(size_t)NQ * 256];
__device__ __align__(128) __half g_Qe [(size_t)NH * NQ * KP_HD];
__device__ __align__(128) __half g_Ke [(size_t)NH * NQ * KP_HD];
__device__ __align__(128) __half g_S  [(size_t)NH * NQ * NQ];     // scores/attn fp16 (134 MB)
__device__ __align__(128) float  g_Vf [(size_t)NH * NQ * VHD];
__device__ __align__(128) __half g_Vte[(size_t)NH * VHD * NQ];    // V^T fp16
__device__ __align__(128) float  g_Xf [(size_t)NQ * LD];
__device__ __align__(128) __half g_Xe [(size_t)NQ * KP_LD2];

// ---------------- PTX helpers (baseline, sm_80+) ----------------
__device__ __forceinline__ uint32_t smem_u32_of(const void* p) {
    uint32_t a;
    asm("{ .reg .u64 t; cvta.to.shared.u64 t, %1; cvt.u32.u64 %0, t; }"
        : "=r"(a) : "l"(p));
    return a;
}

__device__ __forceinline__ void cp16(uint32_t dst, const void* src) {
    asm volatile("cp.async.cg.shared.global [%0], [%1], 16;" :: "r"(dst), "l"(src));
}
__device__ __forceinline__ void cp_commit() {
    asm volatile("cp.async.commit_group;");
}
__device__ __forceinline__ void cp_wait1() {
    asm volatile("cp.async.wait_group 1;");
}

__device__ __forceinline__ void ldsm4(uint32_t* r, uint32_t addr) {
    asm volatile("ldmatrix.sync.aligned.m8n8.x4.shared.b16 {%0,%1,%2,%3}, [%4];"
                 : "=r"(r[0]), "=r"(r[1]), "=r"(r[2]), "=r"(r[3]) : "r"(addr));
}

__device__ __forceinline__ void mma16816(float* c, const uint32_t* a,
                                         uint32_t b0, uint32_t b1) {
    asm volatile(
        "mma.sync.aligned.m16n8k16.row.col.f32.f16.f16.f32 "
        "{%0,%1,%2,%3}, {%4,%5,%6,%7}, {%8,%9}, {%0,%1,%2,%3};"
        : "+f"(c[0]), "+f"(c[1]), "+f"(c[2]), "+f"(c[3])
        : "r"(a[0]), "r"(a[1]), "r"(a[2]), "r"(a[3]), "r"(b0), "r"(b1));
}

// ---------------- fp16 split helpers ----------------
__device__ __forceinline__ __half h_hi(float f) { return __float2half(f); }
__device__ __forceinline__ __half h_lo(float f) {
    float hi = __half2float(__float2half(f));
    return __float2half(f - hi);
}

// ===========================================================================
// HMMA GEMM: C[M, N] = alpha * A @ B^T (+bias) (+C), optional split-K,
// optional fp16 output. A [M, K] fp16 K-major, B [N, K] fp16 K-major,
// (K/splitK) % 64 == 0, N % 128 == 0, M % 128 == 0.
// Tile 128x128, BK=64, 3 cp.async stages, 256 threads, 2 CTAs/SM.
// ===========================================================================
#define STAGE_BYTES 36864
#define NSTAGE 3
#define MMA_SMEM (NSTAGE * STAGE_BYTES)

__device__ __forceinline__ void load_stage(uint32_t sbase,
                                           const __half* A, const __half* B,
                                           int lda, int ldb, int row0, int col0, int k0,
                                           int tid)
{
#pragma unroll
    for (int i = 0; i < 4; i++) {
        int c = tid + i * 256;              // 0..1023
        int r = c >> 3, cc = c & 7;         // row, 16B chunk within 64-col tile
        cp16(sbase + r * 144 + cc * 16,
             A + (size_t)(row0 + r) * lda + k0 + cc * 8);
        cp16(sbase + 18432 + r * 144 + cc * 16,
             B + (size_t)(col0 + r) * ldb + k0 + cc * 8);
    }
}

__global__ __launch_bounds__(256, 2)
void mma_gemm(const __half* __restrict__ A, const __half* __restrict__ B,
              void* __restrict__ Cv, int K, int lda, int ldb, int ldc,
              long long sA, long long sB, long long sC,
              float alpha, const float* __restrict__ bias, int biasN, long long sBias,
              int accum, int splitK, int outHalf)
{
    extern __shared__ char smem[];
    const uint32_t sb = smem_u32_of(smem);
    const int tid = threadIdx.x;
    const int warp = tid >> 5, lane = tid & 31;
    const int wm = warp & 1;                // M half (64 rows)
    const int wn = warp >> 1;               // N quarter (32 cols)

    const int z = blockIdx.z;
    const int batch = z / splitK;
    const int split = z - batch * splitK;
    const int Keff = K / splitK;

    A += (size_t)batch * sA + (size_t)split * Keff;
    B += (size_t)batch * sB + (size_t)split * Keff;
    float* Cf = (float*)Cv + (size_t)batch * sC;
    __half* Ch = (__half*)Cv + (size_t)batch * sC;
    if (bias) bias += (size_t)batch * sBias;
    const int row0 = blockIdx.y * 128, col0 = blockIdx.x * 128;

    float acc[4][4][4];
#pragma unroll
    for (int i = 0; i < 4; i++)
#pragma unroll
        for (int j = 0; j < 4; j++)
#pragma unroll
            for (int v = 0; v < 4; v++) acc[i][j][v] = 0.f;

    const int KT = Keff >> 6;

    // prefetch NSTAGE-1 stages
#pragma unroll
    for (int s = 0; s < NSTAGE - 1; s++) {
        if (s < KT) load_stage(sb + s * STAGE_BYTES, A, B, lda, ldb, row0, col0, s * 64, tid);
        cp_commit();
    }

    const int lrow = lane & 15;             // row within 16
    const int lkof = (lane >> 4) * 16;      // byte offset for k-half (8 fp16)

    for (int kt = 0; kt < KT; kt++) {
        cp_wait1();              // stage kt group complete (this thread)
        __syncthreads();         // all threads see stage kt; oldest stage free

        int ldk = kt + NSTAGE - 1;
        if (ldk < KT)
            load_stage(sb + (ldk % NSTAGE) * STAGE_BYTES, A, B, lda, ldb, row0, col0, ldk * 64, tid);
        cp_commit();

        uint32_t abase = sb + (kt % NSTAGE) * STAGE_BYTES + (wm * 64) * 144;
        uint32_t bbase = sb + (kt % NSTAGE) * STAGE_BYTES + 18432 + (wn * 32) * 144;

#pragma unroll
        for (int k16 = 0; k16 < 4; k16++) {
            uint32_t a[4][4];
#pragma unroll
            for (int mf = 0; mf < 4; mf++)
                ldsm4(a[mf], abase + (mf * 16 + lrow) * 144 + k16 * 32 + lkof);
            uint32_t b[2][4];
#pragma unroll
            for (int nf2 = 0; nf2 < 2; nf2++)
                ldsm4(b[nf2], bbase + (nf2 * 16 + lrow) * 144 + k16 * 32 + lkof);
#pragma unroll
            for (int mf = 0; mf < 4; mf++)
#pragma unroll
                for (int nf = 0; nf < 4; nf++)
                    mma16816(acc[mf][nf], a[mf], b[nf >> 1][nf & 1], b[nf >> 1][2 + (nf & 1)]);
        }
    }

    // -------- epilogue --------
    const int qr = lane >> 2;           // 0..7
    const int qc = (lane & 3) * 2;      // 0,2,4,6
#pragma unroll
    for (int mf = 0; mf < 4; mf++) {
#pragma unroll
        for (int nf = 0; nf < 4; nf++) {
            int gr = row0 + wm * 64 + mf * 16 + qr;
            int gc = col0 + wn * 32 + nf * 8 + qc;
            float b0 = 0.f, b1 = 0.f;
            if (bias && split == 0) {
                if (gc + 0 < biasN) b0 = bias[gc + 0];
                if (gc + 1 < biasN) b1 = bias[gc + 1];
            }
#pragma unroll
            for (int h = 0; h < 2; h++) {
                int r = gr + h * 8;
                float v0 = alpha * acc[mf][nf][h * 2 + 0] + b0;
                float v1 = alpha * acc[mf][nf][h * 2 + 1] + b1;
                if (outHalf) {
                    __half2 o;
                    o.x = __float2half(v0);
                    o.y = __float2half(v1);
                    *(__half2*)(Ch + (size_t)r * ldc + gc) = o;
                } else {
                    float* cp = Cf + (size_t)r * ldc + gc;
                    if (splitK > 1) {
                        atomicAdd(cp + 0, v0);
                        atomicAdd(cp + 1, v1);
                    } else {
                        if (accum) { v0 += cp[0]; v1 += cp[1]; }
                        float2 o = make_float2(v0, v1);
                        *(float2*)cp = o;
                    }
                }
            }
        }
    }
}

// ===========================================================================
// Conversion kernels
// ===========================================================================
// A-side row expansion: fp32 [M,Kin] -> fp16 [M,Kp], term b at cols
// [b*Kin,(b+1)*Kin): b==loIdx -> lo, else hi; zero pad beyond terms*Kin.
__global__ void ext_rows(const float* __restrict__ in, __half* __restrict__ out,
                         int Kin, int ldin, int Kp, int terms, int loIdx)
{
    int c = blockIdx.x * 256 + threadIdx.x;
    if (c >= Kp) return;
    size_t row = blockIdx.y;
    int b = c / Kin;
    __half r;
    if (b >= terms) r = __float2half(0.f);
    else {
        float f = in[row * ldin + (c - b * Kin)];
        r = (b == loIdx) ? h_lo(f) : h_hi(f);
    }
    out[row * (size_t)Kp + c] = r;
}

// B-side transpose expansion: W fp32 [K, Nn] (ldw) -> fp16 [Np, Kp],
// out[n, b*Kin + k] = (b==loIdx ? lo : hi)(W[k, n]); rows n in [Nn,Np) zero.
__global__ void ext_transpose(const float* __restrict__ in, __half* __restrict__ out,
                              int Kin, int Nn, int Np, int Kp, int ldw,
                              long long sIn, long long sOut, int terms, int loIdx)
{
    __shared__ float t[32][33];
    int b = blockIdx.z % terms, z = blockIdx.z / terms;
    in  += (size_t)z * sIn;
    out += (size_t)z * sOut;
    int k0 = blockIdx.x * 32, n0 = blockIdx.y * 32;
    int tx = threadIdx.x, ty = threadIdx.y;   // 32 x 8
#pragma unroll
    for (int i = 0; i < 4; i++) {
        int k = k0 + ty + i * 8, n = n0 + tx;
        t[ty + i * 8][tx] = (k < Kin && n < Nn) ? in[(size_t)k * ldw + n] : 0.f;
    }
    __syncthreads();
#pragma unroll
    for (int i = 0; i < 4; i++) {
        int n = n0 + ty + i * 8, k = k0 + tx;
        if (n < Np && k < Kin) {
            float f = t[tx][ty + i * 8];
            out[(size_t)n * Kp + (size_t)b * Kin + k] = (b == loIdx) ? h_lo(f) : h_hi(f);
        }
    }
}

// Split Q/K fp32 [4096,256] into per-head fp16 [H,4096,64] (cols >= 36 zero).
__global__ void qk_split(const float* __restrict__ Qf, __half* __restrict__ out)
{
    int h = blockIdx.y, row = blockIdx.x, c = threadIdx.x;   // 64 threads
    const float* src = Qf + (size_t)row * 256 + h * HD;
    out[((size_t)h * NQ + row) * KP_HD + c] =
        (c < HD) ? h_hi(src[c]) : __float2half(0.f);
}

// Softmax over fp16 row of 4096, in place.
__global__ __launch_bounds__(256)
void softmax_ext(__half* __restrict__ S)
{
    __half* p = S + (size_t)blockIdx.x * 4096;
    const int t = threadIdx.x;
    float v[16];
    float mx = -1e30f;
#pragma unroll
    for (int i = 0; i < 16; i++) {
        v[i] = __half2float(p[t + i * 256]);
        mx = fmaxf(mx, v[i]);
    }
    __shared__ float red[256];
    red[t] = mx; __syncthreads();
#pragma unroll
    for (int s = 128; s > 0; s >>= 1) { if (t < s) red[t] = fmaxf(red[t], red[t + s]); __syncthreads(); }
    mx = red[0]; __syncthreads();
    float sum = 0.f;
#pragma unroll
    for (int i = 0; i < 16; i++) { v[i] = __expf(v[i] - mx); sum += v[i]; }
    red[t] = sum; __syncthreads();
#pragma unroll
    for (int s = 128; s > 0; s >>= 1) { if (t < s) red[t] += red[t + s]; __syncthreads(); }
    const float inv = 1.f / red[0];
#pragma unroll
    for (int i = 0; i < 16; i++)
        p[t + i * 256] = __float2half(v[i] * inv);
}

// LayerNorm (row of 3584) fused with A-side 2-term fp16 ext write into [*,7168].
__global__ __launch_bounds__(256)
void ln_ext(const float* __restrict__ X, __half* __restrict__ out,
            const float* __restrict__ g, const float* __restrict__ b)
{
    const int D = LD;   // 3584 = 14*256
    const float* p = X + (size_t)blockIdx.x * D;
    __half* q = out + (size_t)blockIdx.x * KP_LD2;
    const int t = threadIdx.x;
    float v[14];
    float s = 0.f;
#pragma unroll
    for (int i = 0; i < 14; i++) { v[i] = p[t + i * 256]; s += v[i]; }
    __shared__ float red[256];
    red[t] = s; __syncthreads();
#pragma unroll
    for (int st = 128; st > 0; st >>= 1) { if (t < st) red[t] += red[t + st]; __syncthreads(); }
    const float mean = red[0] / (float)D; __syncthreads();
    float sq = 0.f;
#pragma unroll
    for (int i = 0; i < 14; i++) { float d = v[i] - mean; sq += d * d; }
    red[t] = sq; __syncthreads();
#pragma unroll
    for (int st = 128; st > 0; st >>= 1) { if (t < st) red[t] += red[t + st]; __syncthreads(); }
    const float inv = rsqrtf(red[0] / (float)D + 1e-5f);
#pragma unroll
    for (int i = 0; i < 14; i++) {
        int c = t + i * 256;
        float y = (v[i] - mean) * inv * g[c] + b[c];
        __half hi = __float2half(y);
        q[c] = hi;
        q[3584 + c] = __float2half(y - __half2float(hi));
    }
}

// ===========================================================================
// Launcher
// ===========================================================================
extern "C" void kernel_launch(void* const* d_in, const int* in_sizes, int n_in,
                              void* d_out, int out_size)
{
    const float* target  = (const float*)d_in[0];
    const float* source  = (const float*)d_in[1];
    const float* value   = (const float*)d_in[2];
    const float* wq_w    = (const float*)d_in[3];
    const float* wq_b    = (const float*)d_in[4];
    const float* wk_w    = (const float*)d_in[5];
    const float* wk_b    = (const float*)d_in[6];
    const float* wv_w    = (const float*)d_in[7];
    const float* wv_b    = (const float*)d_in[8];
    const float* resid_w = (const float*)d_in[9];
    const float* resid_b = (const float*)d_in[10];
    const float* out_w   = (const float*)d_in[11];
    const float* out_b   = (const float*)d_in[12];
    const float* ln_g    = (const float*)d_in[13];
    const float* ln_b    = (const float*)d_in[14];
    float* out = (float*)d_out;

    __half *pte, *pse, *pve, *pwqe, *pwke, *pwve, *pre, *poe;
    __half *pQe, *pKe, *pS, *pVte, *pXe;
    float *pQf, *pKf, *pVf, *pXf;
    cudaGetSymbolAddress((void**)&pte, g_te);
    cudaGetSymbolAddress((void**)&pse, g_se);
    cudaGetSymbolAddress((void**)&pve, g_ve);
    cudaGetSymbolAddress((void**)&pwqe, g_wqe);
    cudaGetSymbolAddress((void**)&pwke, g_wke);
    cudaGetSymbolAddress((void**)&pwve, g_wve);
    cudaGetSymbolAddress((void**)&pre, g_re);
    cudaGetSymbolAddress((void**)&poe, g_oe);
    cudaGetSymbolAddress((void**)&pQf, g_Qf);
    cudaGetSymbolAddress((void**)&pKf, g_Kf);
    cudaGetSymbolAddress((void**)&pQe, g_Qe);
    cudaGetSymbolAddress((void**)&pKe, g_Ke);
    cudaGetSymbolAddress((void**)&pS, g_S);
    cudaGetSymbolAddress((void**)&pVf, g_Vf);
    cudaGetSymbolAddress((void**)&pVte, g_Vte);
    cudaGetSymbolAddress((void**)&pXf, g_Xf);
    cudaGetSymbolAddress((void**)&pXe, g_Xe);

    cudaFuncSetAttribute(mma_gemm, cudaFuncAttributeMaxDynamicSharedMemorySize, MMA_SMEM);

    // zero pads / split-K accumulators
    cudaMemsetAsync(pwqe, 0, (size_t)256 * KP_RD * sizeof(__half));
    cudaMemsetAsync(pre, 0, (size_t)LD * KP_RD * sizeof(__half));
    cudaMemsetAsync(pKf, 0, (size_t)NQ * 256 * sizeof(float));

    // --- operand conversions ---
    ext_rows<<<dim3(2, NQ), 256>>>(target, pte, RD, RD, KP_RD, 2, 1);       // [hi|lo]
    ext_rows<<<dim3(14, NQ), 256>>>(source, pse, LD, LD, LD, 1, -1);
    ext_rows<<<dim3(14, NQ), 256>>>(value, pve, LD, LD, LD, 1, -1);

    ext_transpose<<<dim3(5, 8, 2), dim3(32, 8)>>>(wq_w, pwqe, RD, RD, 256, KP_RD, RD, 0, 0, 2, -1);   // [hi|hi]
    ext_transpose<<<dim3(112, 8, 1), dim3(32, 8)>>>(wk_w, pwke, LD, RD, 256, LD, RD, 0, 0, 1, -1);
    ext_transpose<<<dim3(112, 28, 4), dim3(32, 8)>>>(wv_w, pwve, LD, VHD, VHD, LD, VHD,
                                                     (long long)LD * VHD, (long long)VHD * LD, 1, -1);
    ext_transpose<<<dim3(5, 112, 2), dim3(32, 8)>>>(resid_w, pre, RD, LD, LD, KP_RD, LD, 0, 0, 2, -1);  // [hi|hi]
    ext_transpose<<<dim3(112, 112, 2), dim3(32, 8)>>>(out_w, poe, LD, LD, LD, KP_LD2, LD, 0, 0, 2, -1); // [hi|hi]

    // --- Q projection (2-term fp16) ---
    mma_gemm<<<dim3(2, 32, 1), 256, MMA_SMEM>>>(
        pte, pwqe, pQf, KP_RD, KP_RD, KP_RD, 256, 0, 0, 0, 1.f, wq_b, RD, 0, 0, 1, 0);
    // --- K projection (1-term fp16, split-K=4 into zeroed Kf) ---
    mma_gemm<<<dim3(2, 32, 4), 256, MMA_SMEM>>>(
        pse, pwke, pKf, LD, LD, LD, 256, 0, 0, 0, 1.f, wk_b, RD, 0, 0, 4, 0);
    qk_split<<<dim3(NQ, NH), KP_HD>>>(pQf, pQe);
    qk_split<<<dim3(NQ, NH), KP_HD>>>(pKf, pKe);

    // --- scores: S[h] = (Q_h @ K_h^T) / 6, fp16 output ---
    mma_gemm<<<dim3(32, 32, NH), 256, MMA_SMEM>>>(
        pQe, pKe, pS, KP_HD, KP_HD, KP_HD, NQ,
        (long long)NQ * KP_HD, (long long)NQ * KP_HD, (long long)NQ * NQ,
        1.f / 6.f, nullptr, 0, 0, 0, 1, 1);

    // --- softmax in place (fp16 attn) ---
    softmax_ext<<<NH * NQ, 256>>>(pS);

    // --- V projection (1-term fp16): Vf[h] = value @ wv[h] + b[h] ---
    mma_gemm<<<dim3(7, 32, NH), 256, MMA_SMEM>>>(
        pve, pwve, pVf, LD, LD, LD, VHD,
        0, (long long)VHD * LD, (long long)NQ * VHD,
        1.f, wv_b, VHD, VHD, 0, 1, 0);

    // --- V^T fp16 for ctx GEMM ---
    ext_transpose<<<dim3(128, 28, 4), dim3(32, 8)>>>(pVf, pVte, NQ, VHD, VHD, NQ, VHD,
                                                     (long long)NQ * VHD, (long long)VHD * NQ, 1, -1);

    // --- residual projection: Xf = target @ resid_w + b (2-term fp16) ---
    mma_gemm<<<dim3(28, 32, 1), 256, MMA_SMEM>>>(
        pte, pre, pXf, KP_RD, KP_RD, KP_RD, LD, 0, 0, 0, 1.f, resid_b, LD, 0, 0, 1, 0);

    // --- ctx: Xf[:, h*896 ..] += attn[h] @ V[h]  (1-term fp16) ---
    mma_gemm<<<dim3(7, 32, NH), 256, MMA_SMEM>>>(
        pS, pVte, pXf, NQ, NQ, NQ, LD,
        (long long)NQ * NQ, (long long)VHD * NQ, (long long)VHD,
        1.f, nullptr, 0, 0, 1, 1, 0);

    // --- layernorm + 2-term fp16 ext ---
    ln_ext<<<NQ, 256>>>(pXf, pXe, ln_g, ln_b);

    // --- output projection (2-term fp16) ---
    mma_gemm<<<dim3(28, 32, 1), 256, MMA_SMEM>>>(
        pXe, poe, out, KP_LD2, KP_LD2, KP_LD2, LD, 0, 0, 0, 1.f, out_b, LD, 0, 0, 1, 0);
}

// round 8
// speedup vs baseline: 9.9421x; 1.2276x over previous
#include <cuda_runtime.h>
#include <cuda_fp16.h>
#include <cstdint>
#include <math.h>

// ===========================================================================
// TRAlign on mma.sync (HMMA) tensor cores — sm_103-safe baseline PTX only.
// All GEMMs fp16 with fp32 accumulate:
//   2-term split [hi|lo]x[hi|hi] (~2^-12): Q proj, resid proj
//   1-term plain fp16 (~2^-11-ish):        K proj, scores, V proj, ctx, out proj
// ===========================================================================

#define NQ 4096
#define LD 3584
#define RD 144
#define NH 4
#define HD 36
#define VHD 896

#define KP_RD   320     // 2*144 = 288 -> 320  (Q proj, resid proj)
#define KP_HD   64      // 36 -> 64            (scores, 1-term)

// ---------------- device scratch ----------------
__device__ __align__(128) __half g_te [(size_t)NQ * KP_RD];
__device__ __align__(128) __half g_se [(size_t)NQ * LD];          // source fp16
__device__ __align__(128) __half g_ve [(size_t)NQ * LD];          // value fp16
__device__ __align__(128) __half g_wqe[(size_t)256 * KP_RD];
__device__ __align__(128) __half g_wke[(size_t)256 * LD];         // wk^T fp16
__device__ __align__(128) __half g_wve[(size_t)NH * VHD * LD];    // wv^T fp16
__device__ __align__(128) __half g_re [(size_t)LD * KP_RD];
__device__ __align__(128) __half g_oe [(size_t)LD * LD];          // out^T fp16 (1-term)
__device__ __align__(128) float  g_Qf [(size_t)NQ * 256];
__device__ __align__(128) float  g_Kf [(size_t)NQ * 256];
__device__ __align__(128) __half g_Qe [(size_t)NH * NQ * KP_HD];
__device__ __align__(128) __half g_Ke [(size_t)NH * NQ * KP_HD];
__device__ __align__(128) __half g_S  [(size_t)NH * NQ * NQ];     // scores/attn fp16 (134 MB)
__device__ __align__(128) float  g_Vf [(size_t)NH * NQ * VHD];
__device__ __align__(128) __half g_Vte[(size_t)NH * VHD * NQ];    // V^T fp16
__device__ __align__(128) float  g_Xf [(size_t)NQ * LD];
__device__ __align__(128) __half g_Xe [(size_t)NQ * LD];          // LN(x) fp16 (1-term)

// ---------------- PTX helpers (baseline, sm_80+) ----------------
__device__ __forceinline__ uint32_t smem_u32_of(const void* p) {
    uint32_t a;
    asm("{ .reg .u64 t; cvta.to.shared.u64 t, %1; cvt.u32.u64 %0, t; }"
        : "=r"(a) : "l"(p));
    return a;
}

__device__ __forceinline__ void cp16(uint32_t dst, const void* src) {
    asm volatile("cp.async.cg.shared.global [%0], [%1], 16;" :: "r"(dst), "l"(src));
}
__device__ __forceinline__ void cp_commit() {
    asm volatile("cp.async.commit_group;");
}
__device__ __forceinline__ void cp_wait1() {
    asm volatile("cp.async.wait_group 1;");
}

__device__ __forceinline__ void ldsm4(uint32_t* r, uint32_t addr) {
    asm volatile("ldmatrix.sync.aligned.m8n8.x4.shared.b16 {%0,%1,%2,%3}, [%4];"
                 : "=r"(r[0]), "=r"(r[1]), "=r"(r[2]), "=r"(r[3]) : "r"(addr));
}

__device__ __forceinline__ void mma16816(float* c, const uint32_t* a,
                                         uint32_t b0, uint32_t b1) {
    asm volatile(
        "mma.sync.aligned.m16n8k16.row.col.f32.f16.f16.f32 "
        "{%0,%1,%2,%3}, {%4,%5,%6,%7}, {%8,%9}, {%0,%1,%2,%3};"
        : "+f"(c[0]), "+f"(c[1]), "+f"(c[2]), "+f"(c[3])
        : "r"(a[0]), "r"(a[1]), "r"(a[2]), "r"(a[3]), "r"(b0), "r"(b1));
}

// ---------------- fp16 split helpers ----------------
__device__ __forceinline__ __half h_hi(float f) { return __float2half(f); }
__device__ __forceinline__ __half h_lo(float f) {
    float hi = __half2float(__float2half(f));
    return __float2half(f - hi);
}

// ===========================================================================
// HMMA GEMM: C[M, N] = alpha * A @ B^T (+bias) (+C), optional split-K,
// optional fp16 output. A [M, K] fp16 K-major, B [N, K] fp16 K-major,
// (K/splitK) % 64 == 0, N % 128 == 0, M % 128 == 0.
// Tile 128x128, BK=64, 3 cp.async stages, 256 threads, 2 CTAs/SM.
// ===========================================================================
#define STAGE_BYTES 36864
#define NSTAGE 3
#define MMA_SMEM (NSTAGE * STAGE_BYTES)

__device__ __forceinline__ void load_stage(uint32_t sbase,
                                           const __half* A, const __half* B,
                                           int lda, int ldb, int row0, int col0, int k0,
                                           int tid)
{
#pragma unroll
    for (int i = 0; i < 4; i++) {
        int c = tid + i * 256;              // 0..1023
        int r = c >> 3, cc = c & 7;         // row, 16B chunk within 64-col tile
        cp16(sbase + r * 144 + cc * 16,
             A + (size_t)(row0 + r) * lda + k0 + cc * 8);
        cp16(sbase + 18432 + r * 144 + cc * 16,
             B + (size_t)(col0 + r) * ldb + k0 + cc * 8);
    }
}

__global__ __launch_bounds__(256, 2)
void mma_gemm(const __half* __restrict__ A, const __half* __restrict__ B,
              void* __restrict__ Cv, int K, int lda, int ldb, int ldc,
              long long sA, long long sB, long long sC,
              float alpha, const float* __restrict__ bias, int biasN, long long sBias,
              int accum, int splitK, int outHalf)
{
    extern __shared__ char smem[];
    const uint32_t sb = smem_u32_of(smem);
    const int tid = threadIdx.x;
    const int warp = tid >> 5, lane = tid & 31;
    const int wm = warp & 1;                // M half (64 rows)
    const int wn = warp >> 1;               // N quarter (32 cols)

    const int z = blockIdx.z;
    const int batch = z / splitK;
    const int split = z - batch * splitK;
    const int Keff = K / splitK;

    A += (size_t)batch * sA + (size_t)split * Keff;
    B += (size_t)batch * sB + (size_t)split * Keff;
    float* Cf = (float*)Cv + (size_t)batch * sC;
    __half* Ch = (__half*)Cv + (size_t)batch * sC;
    if (bias) bias += (size_t)batch * sBias;
    const int row0 = blockIdx.y * 128, col0 = blockIdx.x * 128;

    float acc[4][4][4];
#pragma unroll
    for (int i = 0; i < 4; i++)
#pragma unroll
        for (int j = 0; j < 4; j++)
#pragma unroll
            for (int v = 0; v < 4; v++) acc[i][j][v] = 0.f;

    const int KT = Keff >> 6;

    // prefetch NSTAGE-1 stages
#pragma unroll
    for (int s = 0; s < NSTAGE - 1; s++) {
        if (s < KT) load_stage(sb + s * STAGE_BYTES, A, B, lda, ldb, row0, col0, s * 64, tid);
        cp_commit();
    }

    const int lrow = lane & 15;             // row within 16
    const int lkof = (lane >> 4) * 16;      // byte offset for k-half (8 fp16)

    for (int kt = 0; kt < KT; kt++) {
        cp_wait1();              // stage kt group complete (this thread)
        __syncthreads();         // all threads see stage kt; oldest stage free

        int ldk = kt + NSTAGE - 1;
        if (ldk < KT)
            load_stage(sb + (ldk % NSTAGE) * STAGE_BYTES, A, B, lda, ldb, row0, col0, ldk * 64, tid);
        cp_commit();

        uint32_t abase = sb + (kt % NSTAGE) * STAGE_BYTES + (wm * 64) * 144;
        uint32_t bbase = sb + (kt % NSTAGE) * STAGE_BYTES + 18432 + (wn * 32) * 144;

#pragma unroll
        for (int k16 = 0; k16 < 4; k16++) {
            uint32_t a[4][4];
#pragma unroll
            for (int mf = 0; mf < 4; mf++)
                ldsm4(a[mf], abase + (mf * 16 + lrow) * 144 + k16 * 32 + lkof);
            uint32_t b[2][4];
#pragma unroll
            for (int nf2 = 0; nf2 < 2; nf2++)
                ldsm4(b[nf2], bbase + (nf2 * 16 + lrow) * 144 + k16 * 32 + lkof);
#pragma unroll
            for (int mf = 0; mf < 4; mf++)
#pragma unroll
                for (int nf = 0; nf < 4; nf++)
                    mma16816(acc[mf][nf], a[mf], b[nf >> 1][nf & 1], b[nf >> 1][2 + (nf & 1)]);
        }
    }

    // -------- epilogue --------
    const int qr = lane >> 2;           // 0..7
    const int qc = (lane & 3) * 2;      // 0,2,4,6
#pragma unroll
    for (int mf = 0; mf < 4; mf++) {
#pragma unroll
        for (int nf = 0; nf < 4; nf++) {
            int gr = row0 + wm * 64 + mf * 16 + qr;
            int gc = col0 + wn * 32 + nf * 8 + qc;
            float b0 = 0.f, b1 = 0.f;
            if (bias && split == 0) {
                if (gc + 0 < biasN) b0 = bias[gc + 0];
                if (gc + 1 < biasN) b1 = bias[gc + 1];
            }
#pragma unroll
            for (int h = 0; h < 2; h++) {
                int r = gr + h * 8;
                float v0 = alpha * acc[mf][nf][h * 2 + 0] + b0;
                float v1 = alpha * acc[mf][nf][h * 2 + 1] + b1;
                if (outHalf) {
                    __half2 o;
                    o.x = __float2half(v0);
                    o.y = __float2half(v1);
                    *(__half2*)(Ch + (size_t)r * ldc + gc) = o;
                } else {
                    float* cp = Cf + (size_t)r * ldc + gc;
                    if (splitK > 1) {
                        atomicAdd(cp + 0, v0);
                        atomicAdd(cp + 1, v1);
                    } else {
                        if (accum) { v0 += cp[0]; v1 += cp[1]; }
                        float2 o = make_float2(v0, v1);
                        *(float2*)cp = o;
                    }
                }
            }
        }
    }
}

// ===========================================================================
// Conversion kernels
// ===========================================================================
// A-side row expansion: fp32 [M,Kin] -> fp16 [M,Kp], term b at cols
// [b*Kin,(b+1)*Kin): b==loIdx -> lo, else hi; zero pad beyond terms*Kin.
__global__ void ext_rows(const float* __restrict__ in, __half* __restrict__ out,
                         int Kin, int ldin, int Kp, int terms, int loIdx)
{
    int c = blockIdx.x * 256 + threadIdx.x;
    if (c >= Kp) return;
    size_t row = blockIdx.y;
    int b = c / Kin;
    __half r;
    if (b >= terms) r = __float2half(0.f);
    else {
        float f = in[row * ldin + (c - b * Kin)];
        r = (b == loIdx) ? h_lo(f) : h_hi(f);
    }
    out[row * (size_t)Kp + c] = r;
}

// B-side transpose expansion: W fp32 [K, Nn] (ldw) -> fp16 [Np, Kp],
// out[n, b*Kin + k] = (b==loIdx ? lo : hi)(W[k, n]); rows n in [Nn,Np) zero.
__global__ void ext_transpose(const float* __restrict__ in, __half* __restrict__ out,
                              int Kin, int Nn, int Np, int Kp, int ldw,
                              long long sIn, long long sOut, int terms, int loIdx)
{
    __shared__ float t[32][33];
    int b = blockIdx.z % terms, z = blockIdx.z / terms;
    in  += (size_t)z * sIn;
    out += (size_t)z * sOut;
    int k0 = blockIdx.x * 32, n0 = blockIdx.y * 32;
    int tx = threadIdx.x, ty = threadIdx.y;   // 32 x 8
#pragma unroll
    for (int i = 0; i < 4; i++) {
        int k = k0 + ty + i * 8, n = n0 + tx;
        t[ty + i * 8][tx] = (k < Kin && n < Nn) ? in[(size_t)k * ldw + n] : 0.f;
    }
    __syncthreads();
#pragma unroll
    for (int i = 0; i < 4; i++) {
        int n = n0 + ty + i * 8, k = k0 + tx;
        if (n < Np && k < Kin) {
            float f = t[tx][ty + i * 8];
            out[(size_t)n * Kp + (size_t)b * Kin + k] = (b == loIdx) ? h_lo(f) : h_hi(f);
        }
    }
}

// Split Q/K fp32 [4096,256] into per-head fp16 [H,4096,64] (cols >= 36 zero).
__global__ void qk_split(const float* __restrict__ Qf, __half* __restrict__ out)
{
    int h = blockIdx.y, row = blockIdx.x, c = threadIdx.x;   // 64 threads
    const float* src = Qf + (size_t)row * 256 + h * HD;
    out[((size_t)h * NQ + row) * KP_HD + c] =
        (c < HD) ? h_hi(src[c]) : __float2half(0.f);
}

// Softmax over fp16 row of 4096, in place.
__global__ __launch_bounds__(256)
void softmax_ext(__half* __restrict__ S)
{
    __half* p = S + (size_t)blockIdx.x * 4096;
    const int t = threadIdx.x;
    float v[16];
    float mx = -1e30f;
#pragma unroll
    for (int i = 0; i < 16; i++) {
        v[i] = __half2float(p[t + i * 256]);
        mx = fmaxf(mx, v[i]);
    }
    __shared__ float red[256];
    red[t] = mx; __syncthreads();
#pragma unroll
    for (int s = 128; s > 0; s >>= 1) { if (t < s) red[t] = fmaxf(red[t], red[t + s]); __syncthreads(); }
    mx = red[0]; __syncthreads();
    float sum = 0.f;
#pragma unroll
    for (int i = 0; i < 16; i++) { v[i] = __expf(v[i] - mx); sum += v[i]; }
    red[t] = sum; __syncthreads();
#pragma unroll
    for (int s = 128; s > 0; s >>= 1) { if (t < s) red[t] += red[t + s]; __syncthreads(); }
    const float inv = 1.f / red[0];
#pragma unroll
    for (int i = 0; i < 16; i++)
        p[t + i * 256] = __float2half(v[i] * inv);
}

// LayerNorm (row of 3584) fused with 1-term fp16 write into [*,3584].
__global__ __launch_bounds__(256)
void ln_ext(const float* __restrict__ X, __half* __restrict__ out,
            const float* __restrict__ g, const float* __restrict__ b)
{
    const int D = LD;   // 3584 = 14*256
    const float* p = X + (size_t)blockIdx.x * D;
    __half* q = out + (size_t)blockIdx.x * D;
    const int t = threadIdx.x;
    float v[14];
    float s = 0.f;
#pragma unroll
    for (int i = 0; i < 14; i++) { v[i] = p[t + i * 256]; s += v[i]; }
    __shared__ float red[256];
    red[t] = s; __syncthreads();
#pragma unroll
    for (int st = 128; st > 0; st >>= 1) { if (t < st) red[t] += red[t + st]; __syncthreads(); }
    const float mean = red[0] / (float)D; __syncthreads();
    float sq = 0.f;
#pragma unroll
    for (int i = 0; i < 14; i++) { float d = v[i] - mean; sq += d * d; }
    red[t] = sq; __syncthreads();
#pragma unroll
    for (int st = 128; st > 0; st >>= 1) { if (t < st) red[t] += red[t + st]; __syncthreads(); }
    const float inv = rsqrtf(red[0] / (float)D + 1e-5f);
#pragma unroll
    for (int i = 0; i < 14; i++) {
        int c = t + i * 256;
        float y = (v[i] - mean) * inv * g[c] + b[c];
        q[c] = __float2half(y);
    }
}

// ===========================================================================
// Launcher
// ===========================================================================
extern "C" void kernel_launch(void* const* d_in, const int* in_sizes, int n_in,
                              void* d_out, int out_size)
{
    const float* target  = (const float*)d_in[0];
    const float* source  = (const float*)d_in[1];
    const float* value   = (const float*)d_in[2];
    const float* wq_w    = (const float*)d_in[3];
    const float* wq_b    = (const float*)d_in[4];
    const float* wk_w    = (const float*)d_in[5];
    const float* wk_b    = (const float*)d_in[6];
    const float* wv_w    = (const float*)d_in[7];
    const float* wv_b    = (const float*)d_in[8];
    const float* resid_w = (const float*)d_in[9];
    const float* resid_b = (const float*)d_in[10];
    const float* out_w   = (const float*)d_in[11];
    const float* out_b   = (const float*)d_in[12];
    const float* ln_g    = (const float*)d_in[13];
    const float* ln_b    = (const float*)d_in[14];
    float* out = (float*)d_out;

    __half *pte, *pse, *pve, *pwqe, *pwke, *pwve, *pre, *poe;
    __half *pQe, *pKe, *pS, *pVte, *pXe;
    float *pQf, *pKf, *pVf, *pXf;
    cudaGetSymbolAddress((void**)&pte, g_te);
    cudaGetSymbolAddress((void**)&pse, g_se);
    cudaGetSymbolAddress((void**)&pve, g_ve);
    cudaGetSymbolAddress((void**)&pwqe, g_wqe);
    cudaGetSymbolAddress((void**)&pwke, g_wke);
    cudaGetSymbolAddress((void**)&pwve, g_wve);
    cudaGetSymbolAddress((void**)&pre, g_re);
    cudaGetSymbolAddress((void**)&poe, g_oe);
    cudaGetSymbolAddress((void**)&pQf, g_Qf);
    cudaGetSymbolAddress((void**)&pKf, g_Kf);
    cudaGetSymbolAddress((void**)&pQe, g_Qe);
    cudaGetSymbolAddress((void**)&pKe, g_Ke);
    cudaGetSymbolAddress((void**)&pS, g_S);
    cudaGetSymbolAddress((void**)&pVf, g_Vf);
    cudaGetSymbolAddress((void**)&pVte, g_Vte);
    cudaGetSymbolAddress((void**)&pXf, g_Xf);
    cudaGetSymbolAddress((void**)&pXe, g_Xe);

    cudaFuncSetAttribute(mma_gemm, cudaFuncAttributeMaxDynamicSharedMemorySize, MMA_SMEM);

    // zero pads / split-K accumulators
    cudaMemsetAsync(pwqe, 0, (size_t)256 * KP_RD * sizeof(__half));
    cudaMemsetAsync(pre, 0, (size_t)LD * KP_RD * sizeof(__half));
    cudaMemsetAsync(pKf, 0, (size_t)NQ * 256 * sizeof(float));

    // --- operand conversions ---
    ext_rows<<<dim3(2, NQ), 256>>>(target, pte, RD, RD, KP_RD, 2, 1);       // [hi|lo]
    ext_rows<<<dim3(14, NQ), 256>>>(source, pse, LD, LD, LD, 1, -1);
    ext_rows<<<dim3(14, NQ), 256>>>(value, pve, LD, LD, LD, 1, -1);

    ext_transpose<<<dim3(5, 8, 2), dim3(32, 8)>>>(wq_w, pwqe, RD, RD, 256, KP_RD, RD, 0, 0, 2, -1);   // [hi|hi]
    ext_transpose<<<dim3(112, 8, 1), dim3(32, 8)>>>(wk_w, pwke, LD, RD, 256, LD, RD, 0, 0, 1, -1);
    ext_transpose<<<dim3(112, 28, 4), dim3(32, 8)>>>(wv_w, pwve, LD, VHD, VHD, LD, VHD,
                                                     (long long)LD * VHD, (long long)VHD * LD, 1, -1);
    ext_transpose<<<dim3(5, 112, 2), dim3(32, 8)>>>(resid_w, pre, RD, LD, LD, KP_RD, LD, 0, 0, 2, -1);  // [hi|hi]
    ext_transpose<<<dim3(112, 112, 1), dim3(32, 8)>>>(out_w, poe, LD, LD, LD, LD, LD, 0, 0, 1, -1);     // 1-term

    // --- Q projection (2-term fp16) ---
    mma_gemm<<<dim3(2, 32, 1), 256, MMA_SMEM>>>(
        pte, pwqe, pQf, KP_RD, KP_RD, KP_RD, 256, 0, 0, 0, 1.f, wq_b, RD, 0, 0, 1, 0);
    // --- K projection (1-term fp16, split-K=4 into zeroed Kf) ---
    mma_gemm<<<dim3(2, 32, 4), 256, MMA_SMEM>>>(
        pse, pwke, pKf, LD, LD, LD, 256, 0, 0, 0, 1.f, wk_b, RD, 0, 0, 4, 0);
    qk_split<<<dim3(NQ, NH), KP_HD>>>(pQf, pQe);
    qk_split<<<dim3(NQ, NH), KP_HD>>>(pKf, pKe);

    // --- scores: S[h] = (Q_h @ K_h^T) / 6, fp16 output ---
    mma_gemm<<<dim3(32, 32, NH), 256, MMA_SMEM>>>(
        pQe, pKe, pS, KP_HD, KP_HD, KP_HD, NQ,
        (long long)NQ * KP_HD, (long long)NQ * KP_HD, (long long)NQ * NQ,
        1.f / 6.f, nullptr, 0, 0, 0, 1, 1);

    // --- softmax in place (fp16 attn) ---
    softmax_ext<<<NH * NQ, 256>>>(pS);

    // --- V projection (1-term fp16): Vf[h] = value @ wv[h] + b[h] ---
    mma_gemm<<<dim3(7, 32, NH), 256, MMA_SMEM>>>(
        pve, pwve, pVf, LD, LD, LD, VHD,
        0, (long long)VHD * LD, (long long)NQ * VHD,
        1.f, wv_b, VHD, VHD, 0, 1, 0);

    // --- V^T fp16 for ctx GEMM ---
    ext_transpose<<<dim3(128, 28, 4), dim3(32, 8)>>>(pVf, pVte, NQ, VHD, VHD, NQ, VHD,
                                                     (long long)NQ * VHD, (long long)VHD * NQ, 1, -1);

    // --- residual projection: Xf = target @ resid_w + b (2-term fp16) ---
    mma_gemm<<<dim3(28, 32, 1), 256, MMA_SMEM>>>(
        pte, pre, pXf, KP_RD, KP_RD, KP_RD, LD, 0, 0, 0, 1.f, resid_b, LD, 0, 0, 1, 0);

    // --- ctx: Xf[:, h*896 ..] += attn[h] @ V[h]  (1-term fp16) ---
    mma_gemm<<<dim3(7, 32, NH), 256, MMA_SMEM>>>(
        pS, pVte, pXf, NQ, NQ, NQ, LD,
        (long long)NQ * NQ, (long long)VHD * NQ, (long long)VHD,
        1.f, nullptr, 0, 0, 1, 1, 0);

    // --- layernorm + 1-term fp16 ---
    ln_ext<<<NQ, 256>>>(pXf, pXe, ln_g, ln_b);

    // --- output projection (1-term fp16) ---
    mma_gemm<<<dim3(28, 32, 1), 256, MMA_SMEM>>>(
        pXe, poe, out, LD, LD, LD, LD, 0, 0, 0, 1.f, out_b, LD, 0, 0, 1, 0);
}

// round 9
// speedup vs baseline: 10.2783x; 1.0338x over previous
#include <cuda_runtime.h>
#include <cuda_fp16.h>
#include <cstdint>
#include <math.h>

// ===========================================================================
// TRAlign on mma.sync (HMMA) tensor cores — sm_103-safe baseline PTX only.
// All GEMMs fp16 with fp32 accumulate:
//   2-term split [hi|lo]x[hi|hi] (~2^-12): Q proj, resid proj
//   1-term plain fp16:                     K proj, scores, V proj, ctx, out proj
// R9: multi-stream fork/join inside the captured graph to overlap the
//     V-projection chain and prep/epilogue tails with the critical path.
// ===========================================================================

#define NQ 4096
#define LD 3584
#define RD 144
#define NH 4
#define HD 36
#define VHD 896

#define KP_RD   320     // 2*144 = 288 -> 320  (Q proj, resid proj)
#define KP_HD   64      // 36 -> 64            (scores, 1-term)

// ---------------- device scratch ----------------
__device__ __align__(128) __half g_te [(size_t)NQ * KP_RD];
__device__ __align__(128) __half g_se [(size_t)NQ * LD];          // source fp16
__device__ __align__(128) __half g_ve [(size_t)NQ * LD];          // value fp16
__device__ __align__(128) __half g_wqe[(size_t)256 * KP_RD];
__device__ __align__(128) __half g_wke[(size_t)256 * LD];         // wk^T fp16
__device__ __align__(128) __half g_wve[(size_t)NH * VHD * LD];    // wv^T fp16
__device__ __align__(128) __half g_re [(size_t)LD * KP_RD];
__device__ __align__(128) __half g_oe [(size_t)LD * LD];          // out^T fp16 (1-term)
__device__ __align__(128) float  g_Qf [(size_t)NQ * 256];
__device__ __align__(128) float  g_Kf [(size_t)NQ * 256];
__device__ __align__(128) __half g_Qe [(size_t)NH * NQ * KP_HD];
__device__ __align__(128) __half g_Ke [(size_t)NH * NQ * KP_HD];
__device__ __align__(128) __half g_S  [(size_t)NH * NQ * NQ];     // scores/attn fp16 (134 MB)
__device__ __align__(128) float  g_Vf [(size_t)NH * NQ * VHD];
__device__ __align__(128) __half g_Vte[(size_t)NH * VHD * NQ];    // V^T fp16
__device__ __align__(128) float  g_Xf [(size_t)NQ * LD];
__device__ __align__(128) __half g_Xe [(size_t)NQ * LD];          // LN(x) fp16 (1-term)

// ---------------- PTX helpers (baseline, sm_80+) ----------------
__device__ __forceinline__ uint32_t smem_u32_of(const void* p) {
    uint32_t a;
    asm("{ .reg .u64 t; cvta.to.shared.u64 t, %1; cvt.u32.u64 %0, t; }"
        : "=r"(a) : "l"(p));
    return a;
}

__device__ __forceinline__ void cp16(uint32_t dst, const void* src) {
    asm volatile("cp.async.cg.shared.global [%0], [%1], 16;" :: "r"(dst), "l"(src));
}
__device__ __forceinline__ void cp_commit() {
    asm volatile("cp.async.commit_group;");
}
__device__ __forceinline__ void cp_wait1() {
    asm volatile("cp.async.wait_group 1;");
}

__device__ __forceinline__ void ldsm4(uint32_t* r, uint32_t addr) {
    asm volatile("ldmatrix.sync.aligned.m8n8.x4.shared.b16 {%0,%1,%2,%3}, [%4];"
                 : "=r"(r[0]), "=r"(r[1]), "=r"(r[2]), "=r"(r[3]) : "r"(addr));
}

__device__ __forceinline__ void mma16816(float* c, const uint32_t* a,
                                         uint32_t b0, uint32_t b1) {
    asm volatile(
        "mma.sync.aligned.m16n8k16.row.col.f32.f16.f16.f32 "
        "{%0,%1,%2,%3}, {%4,%5,%6,%7}, {%8,%9}, {%0,%1,%2,%3};"
        : "+f"(c[0]), "+f"(c[1]), "+f"(c[2]), "+f"(c[3])
        : "r"(a[0]), "r"(a[1]), "r"(a[2]), "r"(a[3]), "r"(b0), "r"(b1));
}

// ---------------- fp16 split helpers ----------------
__device__ __forceinline__ __half h_hi(float f) { return __float2half(f); }
__device__ __forceinline__ __half h_lo(float f) {
    float hi = __half2float(__float2half(f));
    return __float2half(f - hi);
}

// ===========================================================================
// HMMA GEMM: C[M, N] = alpha * A @ B^T (+bias) (+C), optional split-K,
// optional fp16 output. A [M, K] fp16 K-major, B [N, K] fp16 K-major,
// (K/splitK) % 64 == 0, N % 128 == 0, M % 128 == 0.
// Tile 128x128, BK=64, 3 cp.async stages, 256 threads, 2 CTAs/SM.
// ===========================================================================
#define STAGE_BYTES 36864
#define NSTAGE 3
#define MMA_SMEM (NSTAGE * STAGE_BYTES)

__device__ __forceinline__ void load_stage(uint32_t sbase,
                                           const __half* A, const __half* B,
                                           int lda, int ldb, int row0, int col0, int k0,
                                           int tid)
{
#pragma unroll
    for (int i = 0; i < 4; i++) {
        int c = tid + i * 256;              // 0..1023
        int r = c >> 3, cc = c & 7;         // row, 16B chunk within 64-col tile
        cp16(sbase + r * 144 + cc * 16,
             A + (size_t)(row0 + r) * lda + k0 + cc * 8);
        cp16(sbase + 18432 + r * 144 + cc * 16,
             B + (size_t)(col0 + r) * ldb + k0 + cc * 8);
    }
}

__global__ __launch_bounds__(256, 2)
void mma_gemm(const __half* __restrict__ A, const __half* __restrict__ B,
              void* __restrict__ Cv, int K, int lda, int ldb, int ldc,
              long long sA, long long sB, long long sC,
              float alpha, const float* __restrict__ bias, int biasN, long long sBias,
              int accum, int splitK, int outHalf)
{
    extern __shared__ char smem[];
    const uint32_t sb = smem_u32_of(smem);
    const int tid = threadIdx.x;
    const int warp = tid >> 5, lane = tid & 31;
    const int wm = warp & 1;                // M half (64 rows)
    const int wn = warp >> 1;               // N quarter (32 cols)

    const int z = blockIdx.z;
    const int batch = z / splitK;
    const int split = z - batch * splitK;
    const int Keff = K / splitK;

    A += (size_t)batch * sA + (size_t)split * Keff;
    B += (size_t)batch * sB + (size_t)split * Keff;
    float* Cf = (float*)Cv + (size_t)batch * sC;
    __half* Ch = (__half*)Cv + (size_t)batch * sC;
    if (bias) bias += (size_t)batch * sBias;
    const int row0 = blockIdx.y * 128, col0 = blockIdx.x * 128;

    float acc[4][4][4];
#pragma unroll
    for (int i = 0; i < 4; i++)
#pragma unroll
        for (int j = 0; j < 4; j++)
#pragma unroll
            for (int v = 0; v < 4; v++) acc[i][j][v] = 0.f;

    const int KT = Keff >> 6;

    // prefetch NSTAGE-1 stages
#pragma unroll
    for (int s = 0; s < NSTAGE - 1; s++) {
        if (s < KT) load_stage(sb + s * STAGE_BYTES, A, B, lda, ldb, row0, col0, s * 64, tid);
        cp_commit();
    }

    const int lrow = lane & 15;             // row within 16
    const int lkof = (lane >> 4) * 16;      // byte offset for k-half (8 fp16)

    for (int kt = 0; kt < KT; kt++) {
        cp_wait1();              // stage kt group complete (this thread)
        __syncthreads();         // all threads see stage kt; oldest stage free

        int ldk = kt + NSTAGE - 1;
        if (ldk < KT)
            load_stage(sb + (ldk % NSTAGE) * STAGE_BYTES, A, B, lda, ldb, row0, col0, ldk * 64, tid);
        cp_commit();

        uint32_t abase = sb + (kt % NSTAGE) * STAGE_BYTES + (wm * 64) * 144;
        uint32_t bbase = sb + (kt % NSTAGE) * STAGE_BYTES + 18432 + (wn * 32) * 144;

#pragma unroll
        for (int k16 = 0; k16 < 4; k16++) {
            uint32_t a[4][4];
#pragma unroll
            for (int mf = 0; mf < 4; mf++)
                ldsm4(a[mf], abase + (mf * 16 + lrow) * 144 + k16 * 32 + lkof);
            uint32_t b[2][4];
#pragma unroll
            for (int nf2 = 0; nf2 < 2; nf2++)
                ldsm4(b[nf2], bbase + (nf2 * 16 + lrow) * 144 + k16 * 32 + lkof);
#pragma unroll
            for (int mf = 0; mf < 4; mf++)
#pragma unroll
                for (int nf = 0; nf < 4; nf++)
                    mma16816(acc[mf][nf], a[mf], b[nf >> 1][nf & 1], b[nf >> 1][2 + (nf & 1)]);
        }
    }

    // -------- epilogue --------
    const int qr = lane >> 2;           // 0..7
    const int qc = (lane & 3) * 2;      // 0,2,4,6
#pragma unroll
    for (int mf = 0; mf < 4; mf++) {
#pragma unroll
        for (int nf = 0; nf < 4; nf++) {
            int gr = row0 + wm * 64 + mf * 16 + qr;
            int gc = col0 + wn * 32 + nf * 8 + qc;
            float b0 = 0.f, b1 = 0.f;
            if (bias && split == 0) {
                if (gc + 0 < biasN) b0 = bias[gc + 0];
                if (gc + 1 < biasN) b1 = bias[gc + 1];
            }
#pragma unroll
            for (int h = 0; h < 2; h++) {
                int r = gr + h * 8;
                float v0 = alpha * acc[mf][nf][h * 2 + 0] + b0;
                float v1 = alpha * acc[mf][nf][h * 2 + 1] + b1;
                if (outHalf) {
                    __half2 o;
                    o.x = __float2half(v0);
                    o.y = __float2half(v1);
                    *(__half2*)(Ch + (size_t)r * ldc + gc) = o;
                } else {
                    float* cp = Cf + (size_t)r * ldc + gc;
                    if (splitK > 1) {
                        atomicAdd(cp + 0, v0);
                        atomicAdd(cp + 1, v1);
                    } else {
                        if (accum) { v0 += cp[0]; v1 += cp[1]; }
                        float2 o = make_float2(v0, v1);
                        *(float2*)cp = o;
                    }
                }
            }
        }
    }
}

// ===========================================================================
// Conversion kernels
// ===========================================================================
__global__ void ext_rows(const float* __restrict__ in, __half* __restrict__ out,
                         int Kin, int ldin, int Kp, int terms, int loIdx)
{
    int c = blockIdx.x * 256 + threadIdx.x;
    if (c >= Kp) return;
    size_t row = blockIdx.y;
    int b = c / Kin;
    __half r;
    if (b >= terms) r = __float2half(0.f);
    else {
        float f = in[row * ldin + (c - b * Kin)];
        r = (b == loIdx) ? h_lo(f) : h_hi(f);
    }
    out[row * (size_t)Kp + c] = r;
}

__global__ void ext_transpose(const float* __restrict__ in, __half* __restrict__ out,
                              int Kin, int Nn, int Np, int Kp, int ldw,
                              long long sIn, long long sOut, int terms, int loIdx)
{
    __shared__ float t[32][33];
    int b = blockIdx.z % terms, z = blockIdx.z / terms;
    in  += (size_t)z * sIn;
    out += (size_t)z * sOut;
    int k0 = blockIdx.x * 32, n0 = blockIdx.y * 32;
    int tx = threadIdx.x, ty = threadIdx.y;   // 32 x 8
#pragma unroll
    for (int i = 0; i < 4; i++) {
        int k = k0 + ty + i * 8, n = n0 + tx;
        t[ty + i * 8][tx] = (k < Kin && n < Nn) ? in[(size_t)k * ldw + n] : 0.f;
    }
    __syncthreads();
#pragma unroll
    for (int i = 0; i < 4; i++) {
        int n = n0 + ty + i * 8, k = k0 + tx;
        if (n < Np && k < Kin) {
            float f = t[tx][ty + i * 8];
            out[(size_t)n * Kp + (size_t)b * Kin + k] = (b == loIdx) ? h_lo(f) : h_hi(f);
        }
    }
}

// Split Q/K fp32 [4096,256] into per-head fp16 [H,4096,64] (cols >= 36 zero).
__global__ void qk_split(const float* __restrict__ Qf, __half* __restrict__ out)
{
    int h = blockIdx.y, row = blockIdx.x, c = threadIdx.x;   // 64 threads
    const float* src = Qf + (size_t)row * 256 + h * HD;
    out[((size_t)h * NQ + row) * KP_HD + c] =
        (c < HD) ? h_hi(src[c]) : __float2half(0.f);
}

// Softmax over fp16 row of 4096, in place.
__global__ __launch_bounds__(256)
void softmax_ext(__half* __restrict__ S)
{
    __half* p = S + (size_t)blockIdx.x * 4096;
    const int t = threadIdx.x;
    float v[16];
    float mx = -1e30f;
#pragma unroll
    for (int i = 0; i < 16; i++) {
        v[i] = __half2float(p[t + i * 256]);
        mx = fmaxf(mx, v[i]);
    }
    __shared__ float red[256];
    red[t] = mx; __syncthreads();
#pragma unroll
    for (int s = 128; s > 0; s >>= 1) { if (t < s) red[t] = fmaxf(red[t], red[t + s]); __syncthreads(); }
    mx = red[0]; __syncthreads();
    float sum = 0.f;
#pragma unroll
    for (int i = 0; i < 16; i++) { v[i] = __expf(v[i] - mx); sum += v[i]; }
    red[t] = sum; __syncthreads();
#pragma unroll
    for (int s = 128; s > 0; s >>= 1) { if (t < s) red[t] += red[t + s]; __syncthreads(); }
    const float inv = 1.f / red[0];
#pragma unroll
    for (int i = 0; i < 16; i++)
        p[t + i * 256] = __float2half(v[i] * inv);
}

// LayerNorm (row of 3584) fused with 1-term fp16 write into [*,3584].
__global__ __launch_bounds__(256)
void ln_ext(const float* __restrict__ X, __half* __restrict__ out,
            const float* __restrict__ g, const float* __restrict__ b)
{
    const int D = LD;   // 3584 = 14*256
    const float* p = X + (size_t)blockIdx.x * D;
    __half* q = out + (size_t)blockIdx.x * D;
    const int t = threadIdx.x;
    float v[14];
    float s = 0.f;
#pragma unroll
    for (int i = 0; i < 14; i++) { v[i] = p[t + i * 256]; s += v[i]; }
    __shared__ float red[256];
    red[t] = s; __syncthreads();
#pragma unroll
    for (int st = 128; st > 0; st >>= 1) { if (t < st) red[t] += red[t + st]; __syncthreads(); }
    const float mean = red[0] / (float)D; __syncthreads();
    float sq = 0.f;
#pragma unroll
    for (int i = 0; i < 14; i++) { float d = v[i] - mean; sq += d * d; }
    red[t] = sq; __syncthreads();
#pragma unroll
    for (int st = 128; st > 0; st >>= 1) { if (t < st) red[t] += red[t + st]; __syncthreads(); }
    const float inv = rsqrtf(red[0] / (float)D + 1e-5f);
#pragma unroll
    for (int i = 0; i < 14; i++) {
        int c = t + i * 256;
        float y = (v[i] - mean) * inv * g[c] + b[c];
        q[c] = __float2half(y);
    }
}

// ===========================================================================
// Launcher — multi-stream fork/join (capture-legal event pattern)
// ===========================================================================
extern "C" void kernel_launch(void* const* d_in, const int* in_sizes, int n_in,
                              void* d_out, int out_size)
{
    const float* target  = (const float*)d_in[0];
    const float* source  = (const float*)d_in[1];
    const float* value   = (const float*)d_in[2];
    const float* wq_w    = (const float*)d_in[3];
    const float* wq_b    = (const float*)d_in[4];
    const float* wk_w    = (const float*)d_in[5];
    const float* wk_b    = (const float*)d_in[6];
    const float* wv_w    = (const float*)d_in[7];
    const float* wv_b    = (const float*)d_in[8];
    const float* resid_w = (const float*)d_in[9];
    const float* resid_b = (const float*)d_in[10];
    const float* out_w   = (const float*)d_in[11];
    const float* out_b   = (const float*)d_in[12];
    const float* ln_g    = (const float*)d_in[13];
    const float* ln_b    = (const float*)d_in[14];
    float* out = (float*)d_out;

    __half *pte, *pse, *pve, *pwqe, *pwke, *pwve, *pre, *poe;
    __half *pQe, *pKe, *pS, *pVte, *pXe;
    float *pQf, *pKf, *pVf, *pXf;
    cudaGetSymbolAddress((void**)&pte, g_te);
    cudaGetSymbolAddress((void**)&pse, g_se);
    cudaGetSymbolAddress((void**)&pve, g_ve);
    cudaGetSymbolAddress((void**)&pwqe, g_wqe);
    cudaGetSymbolAddress((void**)&pwke, g_wke);
    cudaGetSymbolAddress((void**)&pwve, g_wve);
    cudaGetSymbolAddress((void**)&pre, g_re);
    cudaGetSymbolAddress((void**)&poe, g_oe);
    cudaGetSymbolAddress((void**)&pQf, g_Qf);
    cudaGetSymbolAddress((void**)&pKf, g_Kf);
    cudaGetSymbolAddress((void**)&pQe, g_Qe);
    cudaGetSymbolAddress((void**)&pKe, g_Ke);
    cudaGetSymbolAddress((void**)&pS, g_S);
    cudaGetSymbolAddress((void**)&pVf, g_Vf);
    cudaGetSymbolAddress((void**)&pVte, g_Vte);
    cudaGetSymbolAddress((void**)&pXf, g_Xf);
    cudaGetSymbolAddress((void**)&pXe, g_Xe);

    cudaFuncSetAttribute(mma_gemm, cudaFuncAttributeMaxDynamicSharedMemorySize, MMA_SMEM);

    // Lazily created streams/events (first call is the uncaptured correctness
    // run, so nothing is created during graph capture).
    static cudaStream_t s1 = 0, s2 = 0;
    static cudaEvent_t evFork = 0, evQ = 0, evResid = 0, evOE = 0, evVt = 0;
    if (!evFork) {
        cudaStreamCreateWithFlags(&s1, cudaStreamNonBlocking);
        cudaStreamCreateWithFlags(&s2, cudaStreamNonBlocking);
        cudaEventCreateWithFlags(&evFork, cudaEventDisableTiming);
        cudaEventCreateWithFlags(&evQ, cudaEventDisableTiming);
        cudaEventCreateWithFlags(&evResid, cudaEventDisableTiming);
        cudaEventCreateWithFlags(&evOE, cudaEventDisableTiming);
        cudaEventCreateWithFlags(&evVt, cudaEventDisableTiming);
    }

    // ---- fork ----
    cudaEventRecord(evFork, 0);
    cudaStreamWaitEvent(s1, evFork, 0);
    cudaStreamWaitEvent(s2, evFork, 0);

    // ================= stream s1: Q chain, resid chain, out_w ext ==========
    cudaMemsetAsync(pwqe, 0, (size_t)256 * KP_RD * sizeof(__half), s1);
    cudaMemsetAsync(pre, 0, (size_t)LD * KP_RD * sizeof(__half), s1);
    ext_rows<<<dim3(2, NQ), 256, 0, s1>>>(target, pte, RD, RD, KP_RD, 2, 1);   // [hi|lo]
    ext_transpose<<<dim3(5, 8, 2), dim3(32, 8), 0, s1>>>(wq_w, pwqe, RD, RD, 256, KP_RD, RD, 0, 0, 2, -1);
    mma_gemm<<<dim3(2, 32, 1), 256, MMA_SMEM, s1>>>(
        pte, pwqe, pQf, KP_RD, KP_RD, KP_RD, 256, 0, 0, 0, 1.f, wq_b, RD, 0, 0, 1, 0);
    qk_split<<<dim3(NQ, NH), KP_HD, 0, s1>>>(pQf, pQe);
    cudaEventRecord(evQ, s1);
    // resid chain (needs pte, same stream)
    ext_transpose<<<dim3(5, 112, 2), dim3(32, 8), 0, s1>>>(resid_w, pre, RD, LD, LD, KP_RD, LD, 0, 0, 2, -1);
    mma_gemm<<<dim3(28, 32, 1), 256, MMA_SMEM, s1>>>(
        pte, pre, pXf, KP_RD, KP_RD, KP_RD, LD, 0, 0, 0, 1.f, resid_b, LD, 0, 0, 1, 0);
    cudaEventRecord(evResid, s1);
    // out_w ext (needed only by the final GEMM)
    ext_transpose<<<dim3(112, 112, 1), dim3(32, 8), 0, s1>>>(out_w, poe, LD, LD, LD, LD, LD, 0, 0, 1, -1);
    cudaEventRecord(evOE, s1);

    // ================= stream s2: V chain ==================================
    ext_rows<<<dim3(14, NQ), 256, 0, s2>>>(value, pve, LD, LD, LD, 1, -1);
    ext_transpose<<<dim3(112, 28, 4), dim3(32, 8), 0, s2>>>(wv_w, pwve, LD, VHD, VHD, LD, VHD,
                                                            (long long)LD * VHD, (long long)VHD * LD, 1, -1);
    mma_gemm<<<dim3(7, 32, NH), 256, MMA_SMEM, s2>>>(
        pve, pwve, pVf, LD, LD, LD, VHD,
        0, (long long)VHD * LD, (long long)NQ * VHD,
        1.f, wv_b, VHD, VHD, 0, 1, 0);
    ext_transpose<<<dim3(128, 28, 4), dim3(32, 8), 0, s2>>>(pVf, pVte, NQ, VHD, VHD, NQ, VHD,
                                                            (long long)NQ * VHD, (long long)VHD * NQ, 1, -1);
    cudaEventRecord(evVt, s2);

    // ================= default stream: critical path =======================
    cudaMemsetAsync(pKf, 0, (size_t)NQ * 256 * sizeof(float), 0);
    ext_rows<<<dim3(14, NQ), 256, 0, 0>>>(source, pse, LD, LD, LD, 1, -1);
    ext_transpose<<<dim3(112, 8, 1), dim3(32, 8), 0, 0>>>(wk_w, pwke, LD, RD, 256, LD, RD, 0, 0, 1, -1);
    mma_gemm<<<dim3(2, 32, 4), 256, MMA_SMEM, 0>>>(
        pse, pwke, pKf, LD, LD, LD, 256, 0, 0, 0, 1.f, wk_b, RD, 0, 0, 4, 0);
    qk_split<<<dim3(NQ, NH), KP_HD, 0, 0>>>(pKf, pKe);

    cudaStreamWaitEvent(0, evQ, 0);
    // scores: S[h] = (Q_h @ K_h^T) / 6, fp16 output
    mma_gemm<<<dim3(32, 32, NH), 256, MMA_SMEM, 0>>>(
        pQe, pKe, pS, KP_HD, KP_HD, KP_HD, NQ,
        (long long)NQ * KP_HD, (long long)NQ * KP_HD, (long long)NQ * NQ,
        1.f / 6.f, nullptr, 0, 0, 0, 1, 1);
    softmax_ext<<<NH * NQ, 256, 0, 0>>>(pS);

    cudaStreamWaitEvent(0, evResid, 0);
    cudaStreamWaitEvent(0, evVt, 0);
    // ctx: Xf[:, h*896 ..] += attn[h] @ V[h]
    mma_gemm<<<dim3(7, 32, NH), 256, MMA_SMEM, 0>>>(
        pS, pVte, pXf, NQ, NQ, NQ, LD,
        (long long)NQ * NQ, (long long)VHD * NQ, (long long)VHD,
        1.f, nullptr, 0, 0, 1, 1, 0);

    ln_ext<<<NQ, 256, 0, 0>>>(pXf, pXe, ln_g, ln_b);

    cudaStreamWaitEvent(0, evOE, 0);
    // output projection (1-term fp16)
    mma_gemm<<<dim3(28, 32, 1), 256, MMA_SMEM, 0>>>(
        pXe, poe, out, LD, LD, LD, LD, 0, 0, 0, 1.f, out_b, LD, 0, 0, 1, 0);
}